// round 1
// baseline (speedup 1.0000x reference)
#include <cuda_runtime.h>
#include <cuda_bf16.h>

#define N_NODES 50000
#define N_EDGES 800000
#define IN_DIM  256
#define HID     128
#define OUT_DIM 3
#define EDGE_DIM 4
#define N_LAYERS 4

// ---------------- static device scratch (no allocations allowed) -------------
__device__ float  g_x  [N_NODES * HID];     // node features (updated in place)
__device__ float  g_P1 [N_NODES * HID];     // x @ W1 (src projection)
__device__ float  g_P2 [N_NODES * HID];     // x @ W2 + b_msg (dst projection)
__device__ int    g_deg[N_NODES];
__device__ int    g_cur[N_NODES];
__device__ int    g_off[N_NODES + 1];
__device__ int    g_csr_src[N_EDGES];
__device__ float4 g_csr_ea [N_EDGES];       // edge_attr permuted into CSR order

// ---------------- CSR build ---------------------------------------------------
__global__ void count_deg_kernel(const int* __restrict__ ei) {
    int e = blockIdx.x * blockDim.x + threadIdx.x;
    if (e < N_EDGES) {
        int dst = ei[N_EDGES + e];
        atomicAdd(&g_deg[dst], 1);
    }
}

// single-block exclusive scan over g_deg -> g_off
__global__ void scan_deg_kernel() {
    __shared__ int warp_sums[32];
    __shared__ int s_carry;
    int tid  = threadIdx.x;
    int lane = tid & 31;
    int wid  = tid >> 5;
    if (tid == 0) s_carry = 0;
    __syncthreads();

    for (int base = 0; base < N_NODES; base += 1024) {
        int v = base + tid;
        int d = (v < N_NODES) ? g_deg[v] : 0;
        // warp inclusive scan
        int x = d;
        #pragma unroll
        for (int o = 1; o < 32; o <<= 1) {
            int y = __shfl_up_sync(0xFFFFFFFFu, x, o);
            if (lane >= o) x += y;
        }
        if (lane == 31) warp_sums[wid] = x;
        __syncthreads();
        if (wid == 0) {
            int w = warp_sums[lane];
            #pragma unroll
            for (int o = 1; o < 32; o <<= 1) {
                int y = __shfl_up_sync(0xFFFFFFFFu, w, o);
                if (lane >= o) w += y;
            }
            warp_sums[lane] = w;
        }
        __syncthreads();
        int prefix = (wid > 0) ? warp_sums[wid - 1] : 0;
        int incl   = x + prefix;
        int carry  = s_carry;
        if (v < N_NODES) g_off[v] = carry + incl - d;
        int total = warp_sums[31];
        __syncthreads();
        if (tid == 0) s_carry = carry + total;
        __syncthreads();
    }
    if (tid == 0) g_off[N_NODES] = N_EDGES;
}

__global__ void fill_csr_kernel(const int* __restrict__ ei,
                                const float* __restrict__ ea) {
    int e = blockIdx.x * blockDim.x + threadIdx.x;
    if (e >= N_EDGES) return;
    int src = ei[e];
    int dst = ei[N_EDGES + e];
    int pos = g_off[dst] + atomicAdd(&g_cur[dst], 1);
    g_csr_src[pos] = src;
    g_csr_ea[pos]  = *(const float4*)(ea + (size_t)e * 4);
}

// ---------------- generic tiled fp32 GEMM: C[M,Nc] = A[M,K]@B[K,Nc] + bias ----
#define BM 64
#define BN 64
#define BK 16

__global__ __launch_bounds__(256)
void gemm_bias_kernel(const float* __restrict__ A, const float* __restrict__ B,
                      const float* __restrict__ bias, float* __restrict__ C,
                      int M, int Nc, int K) {
    __shared__ float As[BK][BM];   // A tile stored transposed
    __shared__ float Bs[BK][BN];

    int tid = threadIdx.x;           // 256 threads
    int tx = tid & 15;               // 0..15 -> 4 cols each
    int ty = tid >> 4;               // 0..15 -> 4 rows each
    int rowBase = blockIdx.y * BM;
    int colBase = blockIdx.x * BN;

    // loader mapping
    int ar = tid >> 2;               // 0..63
    int ac = (tid & 3) * 4;          // 0,4,8,12
    int br = tid >> 4;               // 0..15
    int bc = (tid & 15) * 4;         // 0..60

    float acc[4][4] = {};

    for (int k0 = 0; k0 < K; k0 += BK) {
        float4 av = make_float4(0.f, 0.f, 0.f, 0.f);
        int gr = rowBase + ar;
        if (gr < M) av = *(const float4*)(A + (size_t)gr * K + k0 + ac);
        As[ac + 0][ar] = av.x;
        As[ac + 1][ar] = av.y;
        As[ac + 2][ar] = av.z;
        As[ac + 3][ar] = av.w;

        float4 bv = *(const float4*)(B + (size_t)(k0 + br) * Nc + colBase + bc);
        *(float4*)&Bs[br][bc] = bv;
        __syncthreads();

        #pragma unroll
        for (int kk = 0; kk < BK; ++kk) {
            float4 a = *(const float4*)&As[kk][ty * 4];
            float4 b = *(const float4*)&Bs[kk][tx * 4];
            acc[0][0] += a.x * b.x; acc[0][1] += a.x * b.y; acc[0][2] += a.x * b.z; acc[0][3] += a.x * b.w;
            acc[1][0] += a.y * b.x; acc[1][1] += a.y * b.y; acc[1][2] += a.y * b.z; acc[1][3] += a.y * b.w;
            acc[2][0] += a.z * b.x; acc[2][1] += a.z * b.y; acc[2][2] += a.z * b.z; acc[2][3] += a.z * b.w;
            acc[3][0] += a.w * b.x; acc[3][1] += a.w * b.y; acc[3][2] += a.w * b.z; acc[3][3] += a.w * b.w;
        }
        __syncthreads();
    }

    float4 bb = make_float4(0.f, 0.f, 0.f, 0.f);
    if (bias) bb = *(const float4*)(bias + colBase + tx * 4);
    #pragma unroll
    for (int i = 0; i < 4; ++i) {
        int gr = rowBase + ty * 4 + i;
        if (gr < M) {
            float4 o;
            o.x = acc[i][0] + bb.x;
            o.y = acc[i][1] + bb.y;
            o.z = acc[i][2] + bb.z;
            o.w = acc[i][3] + bb.w;
            *(float4*)(C + (size_t)gr * Nc + colBase + tx * 4) = o;
        }
    }
}

// ---------------- edge message + aggregation (warp per dst node) -------------
// msg = relu(P1[src] + P2[dst] + ea @ W3); x[v] += sum(msg over incoming edges)
__global__ __launch_bounds__(256)
void edge_msg_kernel(const float* __restrict__ P1, const float* __restrict__ P2,
                     const float* __restrict__ W3 /* [4,128] */) {
    int warp = (blockIdx.x * blockDim.x + threadIdx.x) >> 5;
    int lane = threadIdx.x & 31;
    if (warp >= N_NODES) return;
    int v = warp;
    int c4 = lane * 4;

    float4 w0 = *(const float4*)(W3 + 0 * HID + c4);
    float4 w1 = *(const float4*)(W3 + 1 * HID + c4);
    float4 w2 = *(const float4*)(W3 + 2 * HID + c4);
    float4 w3 = *(const float4*)(W3 + 3 * HID + c4);
    float4 p2 = *(const float4*)(P2 + (size_t)v * HID + c4);

    float4 acc = make_float4(0.f, 0.f, 0.f, 0.f);
    int e0 = g_off[v];
    int e1 = g_off[v + 1];
    for (int e = e0; e < e1; ++e) {
        int    s  = __ldg(&g_csr_src[e]);
        float4 ea = g_csr_ea[e];
        float4 p1 = *(const float4*)(P1 + (size_t)s * HID + c4);
        float mx = p1.x + p2.x + ea.x * w0.x + ea.y * w1.x + ea.z * w2.x + ea.w * w3.x;
        float my = p1.y + p2.y + ea.x * w0.y + ea.y * w1.y + ea.z * w2.y + ea.w * w3.y;
        float mz = p1.z + p2.z + ea.x * w0.z + ea.y * w1.z + ea.z * w2.z + ea.w * w3.z;
        float mw = p1.w + p2.w + ea.x * w0.w + ea.y * w1.w + ea.z * w2.w + ea.w * w3.w;
        acc.x += fmaxf(mx, 0.f);
        acc.y += fmaxf(my, 0.f);
        acc.z += fmaxf(mz, 0.f);
        acc.w += fmaxf(mw, 0.f);
    }
    float4 xv = *(float4*)(g_x + (size_t)v * HID + c4);
    xv.x += acc.x; xv.y += acc.y; xv.z += acc.z; xv.w += acc.w;
    *(float4*)(g_x + (size_t)v * HID + c4) = xv;
}

// ---------------- output projection (warp per node) --------------------------
__global__ __launch_bounds__(256)
void out_proj_kernel(const float* __restrict__ Wout, const float* __restrict__ bout,
                     float* __restrict__ out) {
    int warp = (blockIdx.x * blockDim.x + threadIdx.x) >> 5;
    int lane = threadIdx.x & 31;
    if (warp >= N_NODES) return;
    int v = warp;

    float s0 = 0.f, s1 = 0.f, s2 = 0.f;
    #pragma unroll
    for (int k = lane; k < HID; k += 32) {
        float xv = g_x[(size_t)v * HID + k];
        s0 += xv * Wout[k * 3 + 0];
        s1 += xv * Wout[k * 3 + 1];
        s2 += xv * Wout[k * 3 + 2];
    }
    #pragma unroll
    for (int o = 16; o > 0; o >>= 1) {
        s0 += __shfl_xor_sync(0xFFFFFFFFu, s0, o);
        s1 += __shfl_xor_sync(0xFFFFFFFFu, s1, o);
        s2 += __shfl_xor_sync(0xFFFFFFFFu, s2, o);
    }
    if (lane == 0) {
        out[v * 3 + 0] = s0 + bout[0];
        out[v * 3 + 1] = s1 + bout[1];
        out[v * 3 + 2] = s2 + bout[2];
    }
}

// ---------------- launch ------------------------------------------------------
extern "C" void kernel_launch(void* const* d_in, const int* in_sizes, int n_in,
                              void* d_out, int out_size) {
    const float* h     = (const float*)d_in[0];
    const int*   ei    = (const int*)  d_in[1];
    const float* ea    = (const float*)d_in[2];
    const float* W_in  = (const float*)d_in[3];
    const float* b_in  = (const float*)d_in[4];
    const float* W_msg = (const float*)d_in[5];
    const float* b_msg = (const float*)d_in[6];
    const float* W_out = (const float*)d_in[7];
    const float* b_out = (const float*)d_in[8];
    float* out = (float*)d_out;

    float *px, *pP1, *pP2;
    int   *pdeg, *pcur;
    cudaGetSymbolAddress((void**)&px,  g_x);
    cudaGetSymbolAddress((void**)&pP1, g_P1);
    cudaGetSymbolAddress((void**)&pP2, g_P2);
    cudaGetSymbolAddress((void**)&pdeg, g_deg);
    cudaGetSymbolAddress((void**)&pcur, g_cur);

    cudaMemsetAsync(pdeg, 0, N_NODES * sizeof(int), 0);
    cudaMemsetAsync(pcur, 0, N_NODES * sizeof(int), 0);

    const int EB = (N_EDGES + 255) / 256;
    count_deg_kernel<<<EB, 256>>>(ei);
    scan_deg_kernel<<<1, 1024>>>();
    fill_csr_kernel<<<EB, 256>>>(ei, ea);

    // input projection: x = h @ W_in + b_in   [50000,256]@[256,128]
    {
        dim3 grid((HID + BN - 1) / BN, (N_NODES + BM - 1) / BM);
        gemm_bias_kernel<<<grid, 256>>>(h, W_in, b_in, px, N_NODES, HID, IN_DIM);
    }

    const int NODE_WARP_BLOCKS = (N_NODES * 32 + 255) / 256;
    for (int l = 0; l < N_LAYERS; ++l) {
        const float* Wl = W_msg + (size_t)l * (2 * HID + EDGE_DIM) * HID;
        dim3 grid((HID + BN - 1) / BN, (N_NODES + BM - 1) / BM);
        // P1 = x @ W1
        gemm_bias_kernel<<<grid, 256>>>(px, Wl, nullptr, pP1, N_NODES, HID, HID);
        // P2 = x @ W2 + b_msg[l]
        gemm_bias_kernel<<<grid, 256>>>(px, Wl + HID * HID, b_msg + l * HID, pP2,
                                        N_NODES, HID, HID);
        // per-edge message + per-node aggregation, x updated in place
        edge_msg_kernel<<<NODE_WARP_BLOCKS, 256>>>(pP1, pP2, Wl + 2 * HID * HID);
    }

    out_proj_kernel<<<NODE_WARP_BLOCKS, 256>>>(W_out, b_out, out);
}

// round 2
// speedup vs baseline: 1.3847x; 1.3847x over previous
#include <cuda_runtime.h>
#include <cuda_bf16.h>

#define N_NODES 50000
#define N_EDGES 800000
#define IN_DIM  256
#define HID     128
#define OUT_DIM 3
#define EDGE_DIM 4
#define N_LAYERS 4

// ---------------- static device scratch (no allocations allowed) -------------
__device__ float  g_x  [N_NODES * HID];     // node features (updated in place)
__device__ float  g_P1 [N_NODES * HID];     // x @ W1 (src projection)
__device__ float  g_P2 [N_NODES * HID];     // x @ W2 + b_msg (dst projection)
__device__ int    g_deg[N_NODES];
__device__ int    g_cur[N_NODES];
__device__ int    g_off[N_NODES + 1];
__device__ int    g_csr_src[N_EDGES];
__device__ float4 g_csr_ea [N_EDGES];       // edge_attr permuted into CSR order

// ---------------- CSR build ---------------------------------------------------
__global__ void count_deg_kernel(const int* __restrict__ ei) {
    int e = blockIdx.x * blockDim.x + threadIdx.x;
    if (e < N_EDGES) {
        int dst = ei[N_EDGES + e];
        atomicAdd(&g_deg[dst], 1);
    }
}

// single-block exclusive scan over g_deg -> g_off
__global__ void scan_deg_kernel() {
    __shared__ int warp_sums[32];
    __shared__ int s_carry;
    int tid  = threadIdx.x;
    int lane = tid & 31;
    int wid  = tid >> 5;
    if (tid == 0) s_carry = 0;
    __syncthreads();

    for (int base = 0; base < N_NODES; base += 1024) {
        int v = base + tid;
        int d = (v < N_NODES) ? g_deg[v] : 0;
        int x = d;
        #pragma unroll
        for (int o = 1; o < 32; o <<= 1) {
            int y = __shfl_up_sync(0xFFFFFFFFu, x, o);
            if (lane >= o) x += y;
        }
        if (lane == 31) warp_sums[wid] = x;
        __syncthreads();
        if (wid == 0) {
            int w = warp_sums[lane];
            #pragma unroll
            for (int o = 1; o < 32; o <<= 1) {
                int y = __shfl_up_sync(0xFFFFFFFFu, w, o);
                if (lane >= o) w += y;
            }
            warp_sums[lane] = w;
        }
        __syncthreads();
        int prefix = (wid > 0) ? warp_sums[wid - 1] : 0;
        int incl   = x + prefix;
        int carry  = s_carry;
        if (v < N_NODES) g_off[v] = carry + incl - d;
        int total = warp_sums[31];
        __syncthreads();
        if (tid == 0) s_carry = carry + total;
        __syncthreads();
    }
    if (tid == 0) g_off[N_NODES] = N_EDGES;
}

__global__ void fill_csr_kernel(const int* __restrict__ ei,
                                const float* __restrict__ ea) {
    int e = blockIdx.x * blockDim.x + threadIdx.x;
    if (e >= N_EDGES) return;
    int src = ei[e];
    int dst = ei[N_EDGES + e];
    int pos = g_off[dst] + atomicAdd(&g_cur[dst], 1);
    g_csr_src[pos] = src;
    g_csr_ea[pos]  = *(const float4*)(ea + (size_t)e * 4);
}

// ---------------- TF32 tensor-core GEMM (N fixed = 128) ----------------------
// C[M,128] = A[M,K] @ B[K,128] (+bias). blockIdx.z selects (B0,bias0,C0) or
// (B1,bias1,C1), so a layer's P1/P2 pair is one launch sharing A through L2.
#define GBM 128
#define GBK 32

__device__ __forceinline__ unsigned f2tf32(float x) {
    unsigned r;
    asm("cvt.rna.tf32.f32 %0, %1;" : "=r"(r) : "f"(x));
    return r;
}

__global__ __launch_bounds__(256, 2)
void gemm_tf32_kernel(const float* __restrict__ A,
                      const float* __restrict__ B0, const float* __restrict__ B1,
                      const float* __restrict__ bias0, const float* __restrict__ bias1,
                      float* __restrict__ C0, float* __restrict__ C1,
                      int M, int K) {
    __shared__ unsigned As[GBM][GBK + 4];     // [row][k]
    __shared__ unsigned Bs[128][GBK + 4];     // [n][k]  (transposed)

    const float* B    = blockIdx.z ? B1    : B0;
    const float* bias = blockIdx.z ? bias1 : bias0;
    float*       C    = blockIdx.z ? C1    : C0;

    int tid  = threadIdx.x;
    int lane = tid & 31;
    int warp = tid >> 5;
    int warpM = warp >> 1;    // 0..3 -> 32 rows each
    int warpN = warp & 1;     // 0..1 -> 64 cols each
    int rowBase = blockIdx.x * GBM;

    float c[2][8][4] = {};    // [m16 tile][n8 tile][frag]

    int a_row = tid >> 1;             // 0..127
    int a_col = (tid & 1) * 16;       // 0 / 16
    int b_k   = tid >> 3;             // 0..31
    int b_n   = (tid & 7) * 16;       // 0..112

    for (int k0 = 0; k0 < K; k0 += GBK) {
        // A tile 128x32
        int gr = rowBase + a_row;
        #pragma unroll
        for (int j = 0; j < 4; ++j) {
            float4 v = make_float4(0.f, 0.f, 0.f, 0.f);
            if (gr < M) v = *(const float4*)(A + (size_t)gr * K + k0 + a_col + j * 4);
            As[a_row][a_col + j * 4 + 0] = f2tf32(v.x);
            As[a_row][a_col + j * 4 + 1] = f2tf32(v.y);
            As[a_row][a_col + j * 4 + 2] = f2tf32(v.z);
            As[a_row][a_col + j * 4 + 3] = f2tf32(v.w);
        }
        // B tile 32x128 -> transposed into Bs[n][k]
        #pragma unroll
        for (int j = 0; j < 4; ++j) {
            float4 v = *(const float4*)(B + (size_t)(k0 + b_k) * 128 + b_n + j * 4);
            Bs[b_n + j * 4 + 0][b_k] = f2tf32(v.x);
            Bs[b_n + j * 4 + 1][b_k] = f2tf32(v.y);
            Bs[b_n + j * 4 + 2][b_k] = f2tf32(v.z);
            Bs[b_n + j * 4 + 3][b_k] = f2tf32(v.w);
        }
        __syncthreads();

        #pragma unroll
        for (int kk = 0; kk < GBK; kk += 8) {
            unsigned a[2][4], b[8][2];
            #pragma unroll
            for (int m = 0; m < 2; ++m) {
                int r = warpM * 32 + m * 16 + (lane >> 2);
                a[m][0] = As[r    ][kk + (lane & 3)];
                a[m][1] = As[r + 8][kk + (lane & 3)];
                a[m][2] = As[r    ][kk + (lane & 3) + 4];
                a[m][3] = As[r + 8][kk + (lane & 3) + 4];
            }
            #pragma unroll
            for (int n = 0; n < 8; ++n) {
                int cc = warpN * 64 + n * 8 + (lane >> 2);
                b[n][0] = Bs[cc][kk + (lane & 3)];
                b[n][1] = Bs[cc][kk + (lane & 3) + 4];
            }
            #pragma unroll
            for (int m = 0; m < 2; ++m)
                #pragma unroll
                for (int n = 0; n < 8; ++n) {
                    asm volatile(
                        "mma.sync.aligned.m16n8k8.row.col.f32.tf32.tf32.f32 "
                        "{%0,%1,%2,%3}, {%4,%5,%6,%7}, {%8,%9}, {%0,%1,%2,%3};\n"
                        : "+f"(c[m][n][0]), "+f"(c[m][n][1]),
                          "+f"(c[m][n][2]), "+f"(c[m][n][3])
                        : "r"(a[m][0]), "r"(a[m][1]), "r"(a[m][2]), "r"(a[m][3]),
                          "r"(b[n][0]), "r"(b[n][1]));
                }
        }
        __syncthreads();
    }

    // epilogue: bias + store (two 8-row halves per m16 tile)
    #pragma unroll
    for (int m = 0; m < 2; ++m) {
        int r0 = rowBase + warpM * 32 + m * 16 + (lane >> 2);
        #pragma unroll
        for (int n = 0; n < 8; ++n) {
            int col = warpN * 64 + n * 8 + (lane & 3) * 2;
            float bb0 = bias ? bias[col]     : 0.f;
            float bb1 = bias ? bias[col + 1] : 0.f;
            if (r0 < M)
                *(float2*)(C + (size_t)r0 * 128 + col) =
                    make_float2(c[m][n][0] + bb0, c[m][n][1] + bb1);
            if (r0 + 8 < M)
                *(float2*)(C + (size_t)(r0 + 8) * 128 + col) =
                    make_float2(c[m][n][2] + bb0, c[m][n][3] + bb1);
        }
    }
}

// ---------------- edge message + aggregation (warp per dst node) -------------
__global__ __launch_bounds__(256)
void edge_msg_kernel(const float* __restrict__ P1, const float* __restrict__ P2,
                     const float* __restrict__ W3 /* [4,128] */) {
    int warp = (blockIdx.x * blockDim.x + threadIdx.x) >> 5;
    int lane = threadIdx.x & 31;
    if (warp >= N_NODES) return;
    int v = warp;
    int c4 = lane * 4;

    float4 w0 = *(const float4*)(W3 + 0 * HID + c4);
    float4 w1 = *(const float4*)(W3 + 1 * HID + c4);
    float4 w2 = *(const float4*)(W3 + 2 * HID + c4);
    float4 w3 = *(const float4*)(W3 + 3 * HID + c4);
    float4 p2 = *(const float4*)(P2 + (size_t)v * HID + c4);

    float4 acc = make_float4(0.f, 0.f, 0.f, 0.f);
    int e0 = g_off[v];
    int e1 = g_off[v + 1];
    for (int e = e0; e < e1; ++e) {
        int    s  = __ldg(&g_csr_src[e]);
        float4 ea = g_csr_ea[e];
        float4 p1 = *(const float4*)(P1 + (size_t)s * HID + c4);
        float mx = p1.x + p2.x + ea.x * w0.x + ea.y * w1.x + ea.z * w2.x + ea.w * w3.x;
        float my = p1.y + p2.y + ea.x * w0.y + ea.y * w1.y + ea.z * w2.y + ea.w * w3.y;
        float mz = p1.z + p2.z + ea.x * w0.z + ea.y * w1.z + ea.z * w2.z + ea.w * w3.z;
        float mw = p1.w + p2.w + ea.x * w0.w + ea.y * w1.w + ea.z * w2.w + ea.w * w3.w;
        acc.x += fmaxf(mx, 0.f);
        acc.y += fmaxf(my, 0.f);
        acc.z += fmaxf(mz, 0.f);
        acc.w += fmaxf(mw, 0.f);
    }
    float4 xv = *(float4*)(g_x + (size_t)v * HID + c4);
    xv.x += acc.x; xv.y += acc.y; xv.z += acc.z; xv.w += acc.w;
    *(float4*)(g_x + (size_t)v * HID + c4) = xv;
}

// ---------------- output projection (warp per node) --------------------------
__global__ __launch_bounds__(256)
void out_proj_kernel(const float* __restrict__ Wout, const float* __restrict__ bout,
                     float* __restrict__ out) {
    int warp = (blockIdx.x * blockDim.x + threadIdx.x) >> 5;
    int lane = threadIdx.x & 31;
    if (warp >= N_NODES) return;
    int v = warp;

    float s0 = 0.f, s1 = 0.f, s2 = 0.f;
    #pragma unroll
    for (int k = lane; k < HID; k += 32) {
        float xv = g_x[(size_t)v * HID + k];
        s0 += xv * Wout[k * 3 + 0];
        s1 += xv * Wout[k * 3 + 1];
        s2 += xv * Wout[k * 3 + 2];
    }
    #pragma unroll
    for (int o = 16; o > 0; o >>= 1) {
        s0 += __shfl_xor_sync(0xFFFFFFFFu, s0, o);
        s1 += __shfl_xor_sync(0xFFFFFFFFu, s1, o);
        s2 += __shfl_xor_sync(0xFFFFFFFFu, s2, o);
    }
    if (lane == 0) {
        out[v * 3 + 0] = s0 + bout[0];
        out[v * 3 + 1] = s1 + bout[1];
        out[v * 3 + 2] = s2 + bout[2];
    }
}

// ---------------- launch ------------------------------------------------------
extern "C" void kernel_launch(void* const* d_in, const int* in_sizes, int n_in,
                              void* d_out, int out_size) {
    const float* h     = (const float*)d_in[0];
    const int*   ei    = (const int*)  d_in[1];
    const float* ea    = (const float*)d_in[2];
    const float* W_in  = (const float*)d_in[3];
    const float* b_in  = (const float*)d_in[4];
    const float* W_msg = (const float*)d_in[5];
    const float* b_msg = (const float*)d_in[6];
    const float* W_out = (const float*)d_in[7];
    const float* b_out = (const float*)d_in[8];
    float* out = (float*)d_out;

    float *px, *pP1, *pP2;
    int   *pdeg, *pcur;
    cudaGetSymbolAddress((void**)&px,  g_x);
    cudaGetSymbolAddress((void**)&pP1, g_P1);
    cudaGetSymbolAddress((void**)&pP2, g_P2);
    cudaGetSymbolAddress((void**)&pdeg, g_deg);
    cudaGetSymbolAddress((void**)&pcur, g_cur);

    cudaMemsetAsync(pdeg, 0, N_NODES * sizeof(int), 0);
    cudaMemsetAsync(pcur, 0, N_NODES * sizeof(int), 0);

    const int EB = (N_EDGES + 255) / 256;
    count_deg_kernel<<<EB, 256>>>(ei);
    scan_deg_kernel<<<1, 1024>>>();
    fill_csr_kernel<<<EB, 256>>>(ei, ea);

    const int MT = (N_NODES + GBM - 1) / GBM;   // 391

    // input projection: x = h @ W_in + b_in   [50000,256]@[256,128]
    {
        dim3 grid(MT, 1, 1);
        gemm_tf32_kernel<<<grid, 256>>>(h, W_in, nullptr, b_in, nullptr,
                                        px, nullptr, N_NODES, IN_DIM);
    }

    const int NODE_WARP_BLOCKS = (N_NODES * 32 + 255) / 256;
    for (int l = 0; l < N_LAYERS; ++l) {
        const float* Wl = W_msg + (size_t)l * (2 * HID + EDGE_DIM) * HID;
        // P1 = x @ W1 ; P2 = x @ W2 + b_msg[l]  (one fused launch, z selects)
        dim3 grid(MT, 1, 2);
        gemm_tf32_kernel<<<grid, 256>>>(px, Wl, Wl + HID * HID,
                                        nullptr, b_msg + l * HID,
                                        pP1, pP2, N_NODES, HID);
        edge_msg_kernel<<<NODE_WARP_BLOCKS, 256>>>(pP1, pP2, Wl + 2 * HID * HID);
    }

    out_proj_kernel<<<NODE_WARP_BLOCKS, 256>>>(W_out, b_out, out);
}

// round 4
// speedup vs baseline: 1.4542x; 1.0502x over previous
#include <cuda_runtime.h>
#include <cuda_bf16.h>

#define N_NODES 50000
#define N_EDGES 800000
#define IN_DIM  256
#define HID     128
#define OUT_DIM 3
#define EDGE_DIM 4
#define N_LAYERS 4

// ---------------- static device scratch (no allocations allowed) -------------
__device__ float  g_x  [N_NODES * HID];
__device__ float  g_P1 [N_NODES * HID];
__device__ float  g_P2 [N_NODES * HID];
__device__ int    g_deg[N_NODES];
__device__ int    g_cur[N_NODES];
__device__ int    g_off[N_NODES + 1];
__device__ int    g_blksum[64];
__device__ int    g_csr_src[N_EDGES];
__device__ float4 g_csr_ea [N_EDGES];

// ---------------- CSR build ---------------------------------------------------
__global__ void count_deg_kernel(const int* __restrict__ ei) {
    int e = blockIdx.x * blockDim.x + threadIdx.x;
    if (e < N_EDGES) {
        int dst = ei[N_EDGES + e];
        atomicAdd(&g_deg[dst], 1);
    }
}

// block-local exclusive scan of g_deg chunk -> g_off, block total -> g_blksum
__global__ __launch_bounds__(1024)
void scan_local_kernel() {
    __shared__ int warp_sums[32];
    int tid  = threadIdx.x;
    int lane = tid & 31;
    int wid  = tid >> 5;
    int v = blockIdx.x * 1024 + tid;
    int d = (v < N_NODES) ? g_deg[v] : 0;
    int x = d;
    #pragma unroll
    for (int o = 1; o < 32; o <<= 1) {
        int y = __shfl_up_sync(0xFFFFFFFFu, x, o);
        if (lane >= o) x += y;
    }
    if (lane == 31) warp_sums[wid] = x;
    __syncthreads();
    if (wid == 0) {
        int w = warp_sums[lane];
        #pragma unroll
        for (int o = 1; o < 32; o <<= 1) {
            int y = __shfl_up_sync(0xFFFFFFFFu, w, o);
            if (lane >= o) w += y;
        }
        warp_sums[lane] = w;
    }
    __syncthreads();
    int prefix = (wid > 0) ? warp_sums[wid - 1] : 0;
    if (v < N_NODES) g_off[v] = prefix + x - d;   // exclusive within block
    if (tid == 1023) g_blksum[blockIdx.x] = prefix + x;
}

// scan the (<=64) block sums
__global__ void scan_blk_kernel(int nblocks) {
    int lane = threadIdx.x;   // 64 threads
    __shared__ int s[65];
    s[lane] = (lane < nblocks) ? g_blksum[lane] : 0;
    __syncthreads();
    if (lane == 0) {
        int acc = 0;
        for (int i = 0; i < nblocks; ++i) { int t = s[i]; s[i] = acc; acc += t; }
    }
    __syncthreads();
    if (lane < nblocks) g_blksum[lane] = s[lane];
}

__global__ __launch_bounds__(1024)
void scan_add_kernel() {
    int v = blockIdx.x * 1024 + threadIdx.x;
    if (v < N_NODES) g_off[v] += g_blksum[blockIdx.x];
    if (v == 0) g_off[N_NODES] = N_EDGES;
}

__global__ void fill_csr_kernel(const int* __restrict__ ei,
                                const float* __restrict__ ea) {
    int e = blockIdx.x * blockDim.x + threadIdx.x;
    if (e >= N_EDGES) return;
    int src = ei[e];
    int dst = ei[N_EDGES + e];
    int pos = g_off[dst] + atomicAdd(&g_cur[dst], 1);
    g_csr_src[pos] = src;
    g_csr_ea[pos]  = *(const float4*)(ea + (size_t)e * 4);
}

// ---------------- TF32 tensor-core GEMM, fragment-layout smem ----------------
// C[M,128] = A[M,K] @ B[K,128] (+bias). blockIdx.z selects {B0,bias0,C0} or
// {B1,bias1,C1} so a layer's P1/P2 pair shares the A stream through L2.
#define GBM 128
#define GBK 32

__device__ __forceinline__ unsigned f2tf32(float x) {
    unsigned r;
    asm("cvt.rna.tf32.f32 %0, %1;" : "=r"(r) : "f"(x));
    return r;
}

// As frag layout: [m16 (8)][kg (4)][lane (32)][j (4)]  -> uint, 16KB
// Bs frag layout: [n8 (16)][kg (4)][lane (32)][j (2)]  -> uint, 16KB
__global__ __launch_bounds__(256, 2)
void gemm_tf32_kernel(const float* __restrict__ A,
                      const float* __restrict__ B0, const float* __restrict__ B1,
                      const float* __restrict__ bias0, const float* __restrict__ bias1,
                      float* __restrict__ C0, float* __restrict__ C1,
                      int M, int K) {
    __shared__ unsigned As[8 * 4 * 32 * 4];   // 8 m16-tiles  (GBM=128)  — FIXED size
    __shared__ unsigned Bs[16 * 4 * 32 * 2];  // 16 n8-tiles

    const float* B    = blockIdx.z ? B1    : B0;
    const float* bias = blockIdx.z ? bias1 : bias0;
    float*       C    = blockIdx.z ? C1    : C0;

    int tid  = threadIdx.x;
    int lane = tid & 31;
    int warp = tid >> 5;
    int warpM = warp >> 1;    // 0..3 : 32 rows
    int warpN = warp & 1;     // 0..1 : 64 cols
    int rowBase = blockIdx.x * GBM;

    float c[2][8][4] = {};

    // A loader mapping: thread -> row (tid>>1), kcol base ((tid&1)*16)
    int a_row = tid >> 1;
    int a_col = (tid & 1) * 16;
    bool arow_ok = (rowBase + a_row) < M;
    const float* Arow = A + (size_t)(rowBase + a_row) * K;
    // B loader mapping: thread -> k row (tid>>3), n base ((tid&7)*16)
    int b_k = tid >> 3;
    int b_n = (tid & 7) * 16;

    // prefetch first A tile into registers
    float4 pa[4];
    #pragma unroll
    for (int j = 0; j < 4; ++j)
        pa[j] = arow_ok ? *(const float4*)(Arow + a_col + j * 4)
                        : make_float4(0.f, 0.f, 0.f, 0.f);

    const int a_m16   = a_row >> 4;          // 0..7
    const int a_jbit  = (a_row >> 3) & 1;    // row-high bit within m16
    const int a_lnrow = (a_row & 7) << 2;    // lane base = (row%8)*4

    for (int k0 = 0; k0 < K; k0 += GBK) {
        // ---- store prefetched A tile into frag layout ----
        #pragma unroll
        for (int j = 0; j < 4; ++j) {
            float v[4] = {pa[j].x, pa[j].y, pa[j].z, pa[j].w};
            #pragma unroll
            for (int t = 0; t < 4; ++t) {
                int k  = a_col + j * 4 + t;           // 0..31
                int kg = k >> 3;
                int ln = a_lnrow | (k & 3);
                int jj = a_jbit | (((k >> 2) & 1) << 1);
                As[(((a_m16 << 2) | kg) << 7) | (ln << 2) | jj] = f2tf32(v[t]);
            }
        }
        // ---- load + store B tile (gmem -> cvt -> frag layout) ----
        #pragma unroll
        for (int j = 0; j < 4; ++j) {
            float4 v = *(const float4*)(B + (size_t)(k0 + b_k) * 128 + b_n + j * 4);
            float vv[4] = {v.x, v.y, v.z, v.w};
            #pragma unroll
            for (int t = 0; t < 4; ++t) {
                int n  = b_n + j * 4 + t;
                int n8 = n >> 3;
                int kg = b_k >> 3;
                int ln = ((n & 7) << 2) | (b_k & 3);
                int jj = (b_k >> 2) & 1;
                Bs[(((n8 << 2) | kg) << 6) | (ln << 1) | jj] = f2tf32(vv[t]);
            }
        }
        __syncthreads();

        // ---- prefetch next A tile (overlaps with MMA) ----
        if (k0 + GBK < K) {
            #pragma unroll
            for (int j = 0; j < 4; ++j)
                pa[j] = arow_ok ? *(const float4*)(Arow + k0 + GBK + a_col + j * 4)
                                : make_float4(0.f, 0.f, 0.f, 0.f);
        }

        // ---- MMA over 4 k-groups ----
        #pragma unroll
        for (int kg = 0; kg < 4; ++kg) {
            unsigned a[2][4], b[8][2];
            #pragma unroll
            for (int m = 0; m < 2; ++m) {
                int m16 = warpM * 2 + m;
                uint4 av = *(const uint4*)&As[(((m16 << 2) | kg) << 7) | (lane << 2)];
                a[m][0] = av.x; a[m][1] = av.y; a[m][2] = av.z; a[m][3] = av.w;
            }
            #pragma unroll
            for (int n = 0; n < 8; ++n) {
                int n8 = warpN * 8 + n;
                uint2 bv = *(const uint2*)&Bs[(((n8 << 2) | kg) << 6) | (lane << 1)];
                b[n][0] = bv.x; b[n][1] = bv.y;
            }
            #pragma unroll
            for (int m = 0; m < 2; ++m)
                #pragma unroll
                for (int n = 0; n < 8; ++n) {
                    asm volatile(
                        "mma.sync.aligned.m16n8k8.row.col.f32.tf32.tf32.f32 "
                        "{%0,%1,%2,%3}, {%4,%5,%6,%7}, {%8,%9}, {%0,%1,%2,%3};\n"
                        : "+f"(c[m][n][0]), "+f"(c[m][n][1]),
                          "+f"(c[m][n][2]), "+f"(c[m][n][3])
                        : "r"(a[m][0]), "r"(a[m][1]), "r"(a[m][2]), "r"(a[m][3]),
                          "r"(b[n][0]), "r"(b[n][1]));
                }
        }
        __syncthreads();
    }

    // ---- epilogue ----
    #pragma unroll
    for (int m = 0; m < 2; ++m) {
        int r0 = rowBase + warpM * 32 + m * 16 + (lane >> 2);
        #pragma unroll
        for (int n = 0; n < 8; ++n) {
            int col = warpN * 64 + n * 8 + (lane & 3) * 2;
            float bb0 = bias ? bias[col]     : 0.f;
            float bb1 = bias ? bias[col + 1] : 0.f;
            if (r0 < M)
                *(float2*)(C + (size_t)r0 * 128 + col) =
                    make_float2(c[m][n][0] + bb0, c[m][n][1] + bb1);
            if (r0 + 8 < M)
                *(float2*)(C + (size_t)(r0 + 8) * 128 + col) =
                    make_float2(c[m][n][2] + bb0, c[m][n][3] + bb1);
        }
    }
}

// ---------------- edge message + aggregation (warp per dst node) -------------
__global__ __launch_bounds__(256)
void edge_msg_kernel(const float* __restrict__ P1, const float* __restrict__ P2,
                     const float* __restrict__ W3 /* [4,128] */) {
    int warp = (blockIdx.x * blockDim.x + threadIdx.x) >> 5;
    int lane = threadIdx.x & 31;
    if (warp >= N_NODES) return;
    int v = warp;
    int c4 = lane * 4;

    float4 w0 = *(const float4*)(W3 + 0 * HID + c4);
    float4 w1 = *(const float4*)(W3 + 1 * HID + c4);
    float4 w2 = *(const float4*)(W3 + 2 * HID + c4);
    float4 w3 = *(const float4*)(W3 + 3 * HID + c4);
    float4 p2 = *(const float4*)(P2 + (size_t)v * HID + c4);

    float4 acc = make_float4(0.f, 0.f, 0.f, 0.f);
    int e0 = g_off[v];
    int e1 = g_off[v + 1];
    int e  = e0;
    // unrolled by 2: two independent gather chains in flight
    for (; e + 1 < e1; e += 2) {
        int    s0  = __ldg(&g_csr_src[e]);
        int    s1  = __ldg(&g_csr_src[e + 1]);
        float4 ea0 = g_csr_ea[e];
        float4 ea1 = g_csr_ea[e + 1];
        float4 pA  = *(const float4*)(P1 + (size_t)s0 * HID + c4);
        float4 pB  = *(const float4*)(P1 + (size_t)s1 * HID + c4);
        float mx, my, mz, mw;
        mx = pA.x + p2.x + ea0.x * w0.x + ea0.y * w1.x + ea0.z * w2.x + ea0.w * w3.x;
        my = pA.y + p2.y + ea0.x * w0.y + ea0.y * w1.y + ea0.z * w2.y + ea0.w * w3.y;
        mz = pA.z + p2.z + ea0.x * w0.z + ea0.y * w1.z + ea0.z * w2.z + ea0.w * w3.z;
        mw = pA.w + p2.w + ea0.x * w0.w + ea0.y * w1.w + ea0.z * w2.w + ea0.w * w3.w;
        acc.x += fmaxf(mx, 0.f); acc.y += fmaxf(my, 0.f);
        acc.z += fmaxf(mz, 0.f); acc.w += fmaxf(mw, 0.f);
        mx = pB.x + p2.x + ea1.x * w0.x + ea1.y * w1.x + ea1.z * w2.x + ea1.w * w3.x;
        my = pB.y + p2.y + ea1.x * w0.y + ea1.y * w1.y + ea1.z * w2.y + ea1.w * w3.y;
        mz = pB.z + p2.z + ea1.x * w0.z + ea1.y * w1.z + ea1.z * w2.z + ea1.w * w3.z;
        mw = pB.w + p2.w + ea1.x * w0.w + ea1.y * w1.w + ea1.z * w2.w + ea1.w * w3.w;
        acc.x += fmaxf(mx, 0.f); acc.y += fmaxf(my, 0.f);
        acc.z += fmaxf(mz, 0.f); acc.w += fmaxf(mw, 0.f);
    }
    if (e < e1) {
        int    s  = __ldg(&g_csr_src[e]);
        float4 ea = g_csr_ea[e];
        float4 pA = *(const float4*)(P1 + (size_t)s * HID + c4);
        float mx = pA.x + p2.x + ea.x * w0.x + ea.y * w1.x + ea.z * w2.x + ea.w * w3.x;
        float my = pA.y + p2.y + ea.x * w0.y + ea.y * w1.y + ea.z * w2.y + ea.w * w3.y;
        float mz = pA.z + p2.z + ea.x * w0.z + ea.y * w1.z + ea.z * w2.z + ea.w * w3.z;
        float mw = pA.w + p2.w + ea.x * w0.w + ea.y * w1.w + ea.z * w2.w + ea.w * w3.w;
        acc.x += fmaxf(mx, 0.f); acc.y += fmaxf(my, 0.f);
        acc.z += fmaxf(mz, 0.f); acc.w += fmaxf(mw, 0.f);
    }
    float4 xv = *(float4*)(g_x + (size_t)v * HID + c4);
    xv.x += acc.x; xv.y += acc.y; xv.z += acc.z; xv.w += acc.w;
    *(float4*)(g_x + (size_t)v * HID + c4) = xv;
}

// ---------------- output projection (warp per node) --------------------------
__global__ __launch_bounds__(256)
void out_proj_kernel(const float* __restrict__ Wout, const float* __restrict__ bout,
                     float* __restrict__ out) {
    int warp = (blockIdx.x * blockDim.x + threadIdx.x) >> 5;
    int lane = threadIdx.x & 31;
    if (warp >= N_NODES) return;
    int v = warp;

    float s0 = 0.f, s1 = 0.f, s2 = 0.f;
    #pragma unroll
    for (int k = lane; k < HID; k += 32) {
        float xv = g_x[(size_t)v * HID + k];
        s0 += xv * Wout[k * 3 + 0];
        s1 += xv * Wout[k * 3 + 1];
        s2 += xv * Wout[k * 3 + 2];
    }
    #pragma unroll
    for (int o = 16; o > 0; o >>= 1) {
        s0 += __shfl_xor_sync(0xFFFFFFFFu, s0, o);
        s1 += __shfl_xor_sync(0xFFFFFFFFu, s1, o);
        s2 += __shfl_xor_sync(0xFFFFFFFFu, s2, o);
    }
    if (lane == 0) {
        out[v * 3 + 0] = s0 + bout[0];
        out[v * 3 + 1] = s1 + bout[1];
        out[v * 3 + 2] = s2 + bout[2];
    }
}

// ---------------- launch ------------------------------------------------------
extern "C" void kernel_launch(void* const* d_in, const int* in_sizes, int n_in,
                              void* d_out, int out_size) {
    const float* h     = (const float*)d_in[0];
    const int*   ei    = (const int*)  d_in[1];
    const float* ea    = (const float*)d_in[2];
    const float* W_in  = (const float*)d_in[3];
    const float* b_in  = (const float*)d_in[4];
    const float* W_msg = (const float*)d_in[5];
    const float* b_msg = (const float*)d_in[6];
    const float* W_out = (const float*)d_in[7];
    const float* b_out = (const float*)d_in[8];
    float* out = (float*)d_out;

    float *px, *pP1, *pP2;
    int   *pdeg, *pcur;
    cudaGetSymbolAddress((void**)&px,  g_x);
    cudaGetSymbolAddress((void**)&pP1, g_P1);
    cudaGetSymbolAddress((void**)&pP2, g_P2);
    cudaGetSymbolAddress((void**)&pdeg, g_deg);
    cudaGetSymbolAddress((void**)&pcur, g_cur);

    cudaMemsetAsync(pdeg, 0, N_NODES * sizeof(int), 0);
    cudaMemsetAsync(pcur, 0, N_NODES * sizeof(int), 0);

    const int EB = (N_EDGES + 255) / 256;
    const int SB = (N_NODES + 1023) / 1024;   // 49
    count_deg_kernel<<<EB, 256>>>(ei);
    scan_local_kernel<<<SB, 1024>>>();
    scan_blk_kernel<<<1, 64>>>(SB);
    scan_add_kernel<<<SB, 1024>>>();
    fill_csr_kernel<<<EB, 256>>>(ei, ea);

    const int MT = (N_NODES + GBM - 1) / GBM;   // 391

    // input projection: x = h @ W_in + b_in
    {
        dim3 grid(MT, 1, 1);
        gemm_tf32_kernel<<<grid, 256>>>(h, W_in, nullptr, b_in, nullptr,
                                        px, nullptr, N_NODES, IN_DIM);
    }

    const int NODE_WARP_BLOCKS = (N_NODES * 32 + 255) / 256;
    for (int l = 0; l < N_LAYERS; ++l) {
        const float* Wl = W_msg + (size_t)l * (2 * HID + EDGE_DIM) * HID;
        dim3 grid(MT, 1, 2);
        gemm_tf32_kernel<<<grid, 256>>>(px, Wl, Wl + HID * HID,
                                        nullptr, b_msg + l * HID,
                                        pP1, pP2, N_NODES, HID);
        edge_msg_kernel<<<NODE_WARP_BLOCKS, 256>>>(pP1, pP2, Wl + 2 * HID * HID);
    }

    out_proj_kernel<<<NODE_WARP_BLOCKS, 256>>>(W_out, b_out, out);
}

// round 5
// speedup vs baseline: 1.5860x; 1.0906x over previous
#include <cuda_runtime.h>
#include <cuda_bf16.h>
#include <cuda_fp16.h>

#define N_NODES 50000
#define N_EDGES 800000
#define IN_DIM  256
#define HID     128
#define OUT_DIM 3
#define EDGE_DIM 4
#define N_LAYERS 4

// ---------------- static device scratch (no allocations allowed) -------------
__device__ float  g_x  [N_NODES * HID];
__device__ __half g_P1h[N_NODES * HID];     // x @ W1 in fp16 (gathered by edges)
__device__ float  g_P2 [N_NODES * HID];     // x @ W2 + b_msg
__device__ int    g_deg[N_NODES];
__device__ int    g_cur[N_NODES];
__device__ int    g_off[N_NODES + 1];
__device__ int    g_blksum[64];
__device__ int    g_csr_src[N_EDGES];
__device__ float4 g_csr_ea [N_EDGES];

// ---------------- CSR build ---------------------------------------------------
__global__ void count_deg_kernel(const int* __restrict__ ei) {
    int e = blockIdx.x * blockDim.x + threadIdx.x;
    if (e < N_EDGES) {
        int dst = ei[N_EDGES + e];
        atomicAdd(&g_deg[dst], 1);
    }
}

__global__ __launch_bounds__(1024)
void scan_local_kernel() {
    __shared__ int warp_sums[32];
    int tid  = threadIdx.x;
    int lane = tid & 31;
    int wid  = tid >> 5;
    int v = blockIdx.x * 1024 + tid;
    int d = (v < N_NODES) ? g_deg[v] : 0;
    int x = d;
    #pragma unroll
    for (int o = 1; o < 32; o <<= 1) {
        int y = __shfl_up_sync(0xFFFFFFFFu, x, o);
        if (lane >= o) x += y;
    }
    if (lane == 31) warp_sums[wid] = x;
    __syncthreads();
    if (wid == 0) {
        int w = warp_sums[lane];
        #pragma unroll
        for (int o = 1; o < 32; o <<= 1) {
            int y = __shfl_up_sync(0xFFFFFFFFu, w, o);
            if (lane >= o) w += y;
        }
        warp_sums[lane] = w;
    }
    __syncthreads();
    int prefix = (wid > 0) ? warp_sums[wid - 1] : 0;
    if (v < N_NODES) g_off[v] = prefix + x - d;
    if (tid == 1023) g_blksum[blockIdx.x] = prefix + x;
}

__global__ void scan_blk_kernel(int nblocks) {
    int lane = threadIdx.x;
    __shared__ int s[65];
    s[lane] = (lane < nblocks) ? g_blksum[lane] : 0;
    __syncthreads();
    if (lane == 0) {
        int acc = 0;
        for (int i = 0; i < nblocks; ++i) { int t = s[i]; s[i] = acc; acc += t; }
    }
    __syncthreads();
    if (lane < nblocks) g_blksum[lane] = s[lane];
}

__global__ __launch_bounds__(1024)
void scan_add_kernel() {
    int v = blockIdx.x * 1024 + threadIdx.x;
    if (v < N_NODES) g_off[v] += g_blksum[blockIdx.x];
    if (v == 0) g_off[N_NODES] = N_EDGES;
}

__global__ void fill_csr_kernel(const int* __restrict__ ei,
                                const float* __restrict__ ea) {
    int e = blockIdx.x * blockDim.x + threadIdx.x;
    if (e >= N_EDGES) return;
    int src = ei[e];
    int dst = ei[N_EDGES + e];
    int pos = g_off[dst] + atomicAdd(&g_cur[dst], 1);
    g_csr_src[pos] = src;
    g_csr_ea[pos]  = *(const float4*)(ea + (size_t)e * 4);
}

// ---------------- TF32 helpers ------------------------------------------------
__device__ __forceinline__ unsigned f2tf32(float x) {
    unsigned r;
    asm("cvt.rna.tf32.f32 %0, %1;" : "=r"(r) : "f"(x));
    return r;
}

#define MMA_TF32(c, a, b)                                                       \
    asm volatile(                                                               \
        "mma.sync.aligned.m16n8k8.row.col.f32.tf32.tf32.f32 "                   \
        "{%0,%1,%2,%3}, {%4,%5,%6,%7}, {%8,%9}, {%0,%1,%2,%3};\n"               \
        : "+f"((c)[0]), "+f"((c)[1]), "+f"((c)[2]), "+f"((c)[3])                \
        : "r"((a)[0]), "r"((a)[1]), "r"((a)[2]), "r"((a)[3]),                   \
          "r"((b)[0]), "r"((b)[1]))

// ---------------- input projection GEMM (K=256, fp32 out) --------------------
// Round-4 proven kernel, single target.
#define GBM 128
#define GBK 32

__global__ __launch_bounds__(256, 2)
void gemm_in_kernel(const float* __restrict__ A, const float* __restrict__ B0,
                    const float* __restrict__ bias0, float* __restrict__ C0,
                    int M, int K) {
    __shared__ unsigned As[8 * 4 * 32 * 4];
    __shared__ unsigned Bs[16 * 4 * 32 * 2];

    int tid  = threadIdx.x;
    int lane = tid & 31;
    int warp = tid >> 5;
    int warpM = warp >> 1;
    int warpN = warp & 1;
    int rowBase = blockIdx.x * GBM;

    float c[2][8][4] = {};

    int a_row = tid >> 1;
    int a_col = (tid & 1) * 16;
    bool arow_ok = (rowBase + a_row) < M;
    const float* Arow = A + (size_t)(rowBase + a_row) * K;
    int b_k = tid >> 3;
    int b_n = (tid & 7) * 16;

    float4 pa[4];
    #pragma unroll
    for (int j = 0; j < 4; ++j)
        pa[j] = arow_ok ? *(const float4*)(Arow + a_col + j * 4)
                        : make_float4(0.f, 0.f, 0.f, 0.f);

    const int a_m16   = a_row >> 4;
    const int a_jbit  = (a_row >> 3) & 1;
    const int a_lnrow = (a_row & 7) << 2;

    for (int k0 = 0; k0 < K; k0 += GBK) {
        #pragma unroll
        for (int j = 0; j < 4; ++j) {
            float v[4] = {pa[j].x, pa[j].y, pa[j].z, pa[j].w};
            #pragma unroll
            for (int t = 0; t < 4; ++t) {
                int k  = a_col + j * 4 + t;
                int kg = k >> 3;
                int ln = a_lnrow | (k & 3);
                int jj = a_jbit | (((k >> 2) & 1) << 1);
                As[(((a_m16 << 2) | kg) << 7) | (ln << 2) | jj] = f2tf32(v[t]);
            }
        }
        #pragma unroll
        for (int j = 0; j < 4; ++j) {
            float4 v = *(const float4*)(B0 + (size_t)(k0 + b_k) * 128 + b_n + j * 4);
            float vv[4] = {v.x, v.y, v.z, v.w};
            #pragma unroll
            for (int t = 0; t < 4; ++t) {
                int n  = b_n + j * 4 + t;
                int n8 = n >> 3;
                int kg = b_k >> 3;
                int ln = ((n & 7) << 2) | (b_k & 3);
                int jj = (b_k >> 2) & 1;
                Bs[(((n8 << 2) | kg) << 6) | (ln << 1) | jj] = f2tf32(vv[t]);
            }
        }
        __syncthreads();

        if (k0 + GBK < K) {
            #pragma unroll
            for (int j = 0; j < 4; ++j)
                pa[j] = arow_ok ? *(const float4*)(Arow + k0 + GBK + a_col + j * 4)
                                : make_float4(0.f, 0.f, 0.f, 0.f);
        }

        #pragma unroll
        for (int kg = 0; kg < 4; ++kg) {
            unsigned a[2][4], b[8][2];
            #pragma unroll
            for (int m = 0; m < 2; ++m) {
                int m16 = warpM * 2 + m;
                uint4 av = *(const uint4*)&As[(((m16 << 2) | kg) << 7) | (lane << 2)];
                a[m][0] = av.x; a[m][1] = av.y; a[m][2] = av.z; a[m][3] = av.w;
            }
            #pragma unroll
            for (int n = 0; n < 8; ++n) {
                int n8 = warpN * 8 + n;
                uint2 bv = *(const uint2*)&Bs[(((n8 << 2) | kg) << 6) | (lane << 1)];
                b[n][0] = bv.x; b[n][1] = bv.y;
            }
            #pragma unroll
            for (int m = 0; m < 2; ++m)
                #pragma unroll
                for (int n = 0; n < 8; ++n)
                    MMA_TF32(c[m][n], a[m], b[n]);
        }
        __syncthreads();
    }

    #pragma unroll
    for (int m = 0; m < 2; ++m) {
        int r0 = rowBase + warpM * 32 + m * 16 + (lane >> 2);
        #pragma unroll
        for (int n = 0; n < 8; ++n) {
            int col = warpN * 64 + n * 8 + (lane & 3) * 2;
            float bb0 = bias0[col];
            float bb1 = bias0[col + 1];
            if (r0 < M)
                *(float2*)(C0 + (size_t)r0 * 128 + col) =
                    make_float2(c[m][n][0] + bb0, c[m][n][1] + bb1);
            if (r0 + 8 < M)
                *(float2*)(C0 + (size_t)(r0 + 8) * 128 + col) =
                    make_float2(c[m][n][2] + bb0, c[m][n][3] + bb1);
        }
    }
}

// ---------------- fused layer GEMM: A staged once, computes P1(half) + P2 ----
// K = 128 fixed. Dynamic smem: As frags 64KB + Bs frags 16KB = 80KB.
#define LAYER_SMEM ((8 * 16 * 32 * 4 + 16 * 4 * 32 * 2) * 4)

__global__ __launch_bounds__(256, 2)
void gemm_layer_kernel(const float* __restrict__ A,
                       const float* __restrict__ B0, const float* __restrict__ B1,
                       const float* __restrict__ bias1,
                       __half* __restrict__ C0, float* __restrict__ C1, int M) {
    extern __shared__ unsigned sm[];
    unsigned* As = sm;            // [m16(8)][kg(16)][lane(32)][j(4)]
    unsigned* Bs = sm + 16384;    // [n8(16)][kg(4)][lane(32)][j(2)]

    int tid  = threadIdx.x;
    int lane = tid & 31;
    int warp = tid >> 5;
    int warpM = warp >> 1;
    int warpN = warp & 1;
    int rowBase = blockIdx.x * 128;

    // ---- stage full A tile (128 rows x 128 k) once ----
    int a_row = tid >> 1;
    int a_cb  = (tid & 1) * 16;
    bool arow_ok = (rowBase + a_row) < M;
    const float* Arow = A + (size_t)(rowBase + a_row) * 128;
    const int a_m16   = a_row >> 4;
    const int a_jbit  = (a_row >> 3) & 1;
    const int a_lnrow = (a_row & 7) << 2;

    #pragma unroll
    for (int kc = 0; kc < 4; ++kc) {
        #pragma unroll
        for (int j = 0; j < 4; ++j) {
            float4 v = arow_ok ? *(const float4*)(Arow + kc * 32 + a_cb + j * 4)
                               : make_float4(0.f, 0.f, 0.f, 0.f);
            float vv[4] = {v.x, v.y, v.z, v.w};
            #pragma unroll
            for (int t = 0; t < 4; ++t) {
                int kl = a_cb + j * 4 + t;             // 0..31 within chunk
                int kg = kc * 4 + (kl >> 3);           // 0..15 global k-group
                int ln = a_lnrow | (kl & 3);
                int jj = a_jbit | (((kl >> 2) & 1) << 1);
                As[(((a_m16 << 4) | kg) << 7) | (ln << 2) | jj] = f2tf32(vv[t]);
            }
        }
    }
    __syncthreads();

    int b_k = tid >> 3;
    int b_n = (tid & 7) * 16;

    #pragma unroll
    for (int t = 0; t < 2; ++t) {
        const float* B = t ? B1 : B0;
        float c[2][8][4] = {};

        for (int kt = 0; kt < 4; ++kt) {
            // stage B k-tile (weights: L2-resident)
            #pragma unroll
            for (int j = 0; j < 4; ++j) {
                float4 v = *(const float4*)(B + (size_t)(kt * 32 + b_k) * 128 + b_n + j * 4);
                float vv[4] = {v.x, v.y, v.z, v.w};
                #pragma unroll
                for (int u = 0; u < 4; ++u) {
                    int n  = b_n + j * 4 + u;
                    int n8 = n >> 3;
                    int kg = b_k >> 3;
                    int ln = ((n & 7) << 2) | (b_k & 3);
                    int jj = (b_k >> 2) & 1;
                    Bs[(((n8 << 2) | kg) << 6) | (ln << 1) | jj] = f2tf32(vv[u]);
                }
            }
            __syncthreads();

            #pragma unroll
            for (int kgl = 0; kgl < 4; ++kgl) {
                int kg = kt * 4 + kgl;
                unsigned a[2][4], b[8][2];
                #pragma unroll
                for (int m = 0; m < 2; ++m) {
                    int m16 = warpM * 2 + m;
                    uint4 av = *(const uint4*)&As[(((m16 << 4) | kg) << 7) | (lane << 2)];
                    a[m][0] = av.x; a[m][1] = av.y; a[m][2] = av.z; a[m][3] = av.w;
                }
                #pragma unroll
                for (int n = 0; n < 8; ++n) {
                    int n8 = warpN * 8 + n;
                    uint2 bv = *(const uint2*)&Bs[(((n8 << 2) | kgl) << 6) | (lane << 1)];
                    b[n][0] = bv.x; b[n][1] = bv.y;
                }
                #pragma unroll
                for (int m = 0; m < 2; ++m)
                    #pragma unroll
                    for (int n = 0; n < 8; ++n)
                        MMA_TF32(c[m][n], a[m], b[n]);
            }
            __syncthreads();
        }

        // ---- epilogue ----
        #pragma unroll
        for (int m = 0; m < 2; ++m) {
            int r0 = rowBase + warpM * 32 + m * 16 + (lane >> 2);
            #pragma unroll
            for (int n = 0; n < 8; ++n) {
                int col = warpN * 64 + n * 8 + (lane & 3) * 2;
                if (t == 0) {   // P1 -> fp16, no bias
                    if (r0 < M)
                        *(__half2*)(C0 + (size_t)r0 * 128 + col) =
                            __floats2half2_rn(c[m][n][0], c[m][n][1]);
                    if (r0 + 8 < M)
                        *(__half2*)(C0 + (size_t)(r0 + 8) * 128 + col) =
                            __floats2half2_rn(c[m][n][2], c[m][n][3]);
                } else {        // P2 -> fp32 + bias
                    float bb0 = bias1[col];
                    float bb1 = bias1[col + 1];
                    if (r0 < M)
                        *(float2*)(C1 + (size_t)r0 * 128 + col) =
                            make_float2(c[m][n][0] + bb0, c[m][n][1] + bb1);
                    if (r0 + 8 < M)
                        *(float2*)(C1 + (size_t)(r0 + 8) * 128 + col) =
                            make_float2(c[m][n][2] + bb0, c[m][n][3] + bb1);
                }
            }
        }
    }
}

// ---------------- edge message + aggregation (warp per dst node) -------------
__device__ __forceinline__ float4 loadP1h(const __half* __restrict__ P1,
                                          int s, int c4) {
    uint2 raw = *(const uint2*)(P1 + (size_t)s * HID + c4);
    __half2 h0 = *reinterpret_cast<__half2*>(&raw.x);
    __half2 h1 = *reinterpret_cast<__half2*>(&raw.y);
    float2 f0 = __half22float2(h0);
    float2 f1 = __half22float2(h1);
    return make_float4(f0.x, f0.y, f1.x, f1.y);
}

__global__ __launch_bounds__(256)
void edge_msg_kernel(const __half* __restrict__ P1, const float* __restrict__ P2,
                     const float* __restrict__ W3 /* [4,128] */) {
    int warp = (blockIdx.x * blockDim.x + threadIdx.x) >> 5;
    int lane = threadIdx.x & 31;
    if (warp >= N_NODES) return;
    int v = warp;
    int c4 = lane * 4;

    float4 w0 = *(const float4*)(W3 + 0 * HID + c4);
    float4 w1 = *(const float4*)(W3 + 1 * HID + c4);
    float4 w2 = *(const float4*)(W3 + 2 * HID + c4);
    float4 w3 = *(const float4*)(W3 + 3 * HID + c4);
    float4 p2 = *(const float4*)(P2 + (size_t)v * HID + c4);

    float4 acc = make_float4(0.f, 0.f, 0.f, 0.f);
    int e0 = g_off[v];
    int e1 = g_off[v + 1];
    int e  = e0;

    #define EDGE_ONE(p1v, eav)                                                        \
        do {                                                                          \
            float mx = (p1v).x + p2.x + (eav).x * w0.x + (eav).y * w1.x +             \
                       (eav).z * w2.x + (eav).w * w3.x;                               \
            float my = (p1v).y + p2.y + (eav).x * w0.y + (eav).y * w1.y +             \
                       (eav).z * w2.y + (eav).w * w3.y;                               \
            float mz = (p1v).z + p2.z + (eav).x * w0.z + (eav).y * w1.z +             \
                       (eav).z * w2.z + (eav).w * w3.z;                               \
            float mw = (p1v).w + p2.w + (eav).x * w0.w + (eav).y * w1.w +             \
                       (eav).z * w2.w + (eav).w * w3.w;                               \
            acc.x += fmaxf(mx, 0.f); acc.y += fmaxf(my, 0.f);                         \
            acc.z += fmaxf(mz, 0.f); acc.w += fmaxf(mw, 0.f);                         \
        } while (0)

    // unrolled by 4: four independent gather chains in flight
    for (; e + 3 < e1; e += 4) {
        int s0 = __ldg(&g_csr_src[e]);
        int s1 = __ldg(&g_csr_src[e + 1]);
        int s2 = __ldg(&g_csr_src[e + 2]);
        int s3 = __ldg(&g_csr_src[e + 3]);
        float4 q0 = loadP1h(P1, s0, c4);
        float4 q1 = loadP1h(P1, s1, c4);
        float4 q2 = loadP1h(P1, s2, c4);
        float4 q3 = loadP1h(P1, s3, c4);
        float4 a0 = g_csr_ea[e];
        float4 a1 = g_csr_ea[e + 1];
        float4 a2 = g_csr_ea[e + 2];
        float4 a3 = g_csr_ea[e + 3];
        EDGE_ONE(q0, a0);
        EDGE_ONE(q1, a1);
        EDGE_ONE(q2, a2);
        EDGE_ONE(q3, a3);
    }
    for (; e < e1; ++e) {
        int s = __ldg(&g_csr_src[e]);
        float4 q = loadP1h(P1, s, c4);
        float4 a = g_csr_ea[e];
        EDGE_ONE(q, a);
    }
    #undef EDGE_ONE

    float4 xv = *(float4*)(g_x + (size_t)v * HID + c4);
    xv.x += acc.x; xv.y += acc.y; xv.z += acc.z; xv.w += acc.w;
    *(float4*)(g_x + (size_t)v * HID + c4) = xv;
}

// ---------------- output projection (warp per node) --------------------------
__global__ __launch_bounds__(256)
void out_proj_kernel(const float* __restrict__ Wout, const float* __restrict__ bout,
                     float* __restrict__ out) {
    int warp = (blockIdx.x * blockDim.x + threadIdx.x) >> 5;
    int lane = threadIdx.x & 31;
    if (warp >= N_NODES) return;
    int v = warp;

    float s0 = 0.f, s1 = 0.f, s2 = 0.f;
    #pragma unroll
    for (int k = lane; k < HID; k += 32) {
        float xv = g_x[(size_t)v * HID + k];
        s0 += xv * Wout[k * 3 + 0];
        s1 += xv * Wout[k * 3 + 1];
        s2 += xv * Wout[k * 3 + 2];
    }
    #pragma unroll
    for (int o = 16; o > 0; o >>= 1) {
        s0 += __shfl_xor_sync(0xFFFFFFFFu, s0, o);
        s1 += __shfl_xor_sync(0xFFFFFFFFu, s1, o);
        s2 += __shfl_xor_sync(0xFFFFFFFFu, s2, o);
    }
    if (lane == 0) {
        out[v * 3 + 0] = s0 + bout[0];
        out[v * 3 + 1] = s1 + bout[1];
        out[v * 3 + 2] = s2 + bout[2];
    }
}

// ---------------- launch ------------------------------------------------------
extern "C" void kernel_launch(void* const* d_in, const int* in_sizes, int n_in,
                              void* d_out, int out_size) {
    const float* h     = (const float*)d_in[0];
    const int*   ei    = (const int*)  d_in[1];
    const float* ea    = (const float*)d_in[2];
    const float* W_in  = (const float*)d_in[3];
    const float* b_in  = (const float*)d_in[4];
    const float* W_msg = (const float*)d_in[5];
    const float* b_msg = (const float*)d_in[6];
    const float* W_out = (const float*)d_in[7];
    const float* b_out = (const float*)d_in[8];
    float* out = (float*)d_out;

    float  *px, *pP2;
    __half *pP1h;
    int    *pdeg, *pcur;
    cudaGetSymbolAddress((void**)&px,   g_x);
    cudaGetSymbolAddress((void**)&pP1h, g_P1h);
    cudaGetSymbolAddress((void**)&pP2,  g_P2);
    cudaGetSymbolAddress((void**)&pdeg, g_deg);
    cudaGetSymbolAddress((void**)&pcur, g_cur);

    cudaFuncSetAttribute(gemm_layer_kernel,
                         cudaFuncAttributeMaxDynamicSharedMemorySize, LAYER_SMEM);

    cudaMemsetAsync(pdeg, 0, N_NODES * sizeof(int), 0);
    cudaMemsetAsync(pcur, 0, N_NODES * sizeof(int), 0);

    const int EB = (N_EDGES + 255) / 256;
    const int SB = (N_NODES + 1023) / 1024;   // 49
    count_deg_kernel<<<EB, 256>>>(ei);
    scan_local_kernel<<<SB, 1024>>>();
    scan_blk_kernel<<<1, 64>>>(SB);
    scan_add_kernel<<<SB, 1024>>>();
    fill_csr_kernel<<<EB, 256>>>(ei, ea);

    const int MT = (N_NODES + GBM - 1) / GBM;   // 391

    // input projection: x = h @ W_in + b_in
    gemm_in_kernel<<<MT, 256>>>(h, W_in, b_in, px, N_NODES, IN_DIM);

    const int NODE_WARP_BLOCKS = (N_NODES * 32 + 255) / 256;
    for (int l = 0; l < N_LAYERS; ++l) {
        const float* Wl = W_msg + (size_t)l * (2 * HID + EDGE_DIM) * HID;
        // fused: P1 = x@W1 (fp16), P2 = x@W2 + b_msg[l] (fp32), A staged once
        gemm_layer_kernel<<<MT, 256, LAYER_SMEM>>>(px, Wl, Wl + HID * HID,
                                                   b_msg + l * HID,
                                                   pP1h, pP2, N_NODES);
        edge_msg_kernel<<<NODE_WARP_BLOCKS, 256>>>(pP1h, pP2, Wl + 2 * HID * HID);
    }

    out_proj_kernel<<<NODE_WARP_BLOCKS, 256>>>(W_out, b_out, out);
}

// round 6
// speedup vs baseline: 1.6002x; 1.0089x over previous
#include <cuda_runtime.h>
#include <cuda_bf16.h>
#include <cuda_fp16.h>

#define N_NODES 50000
#define N_EDGES 800000
#define IN_DIM  256
#define HID     128
#define OUT_DIM 3
#define EDGE_DIM 4
#define N_LAYERS 4

// ---------------- static device scratch (no allocations allowed) -------------
__device__ float  g_x  [N_NODES * HID];
__device__ __half g_P1h[N_NODES * HID];     // x @ W1 in fp16 (gathered by edges)
__device__ float  g_P2 [N_NODES * HID];     // x @ W2 + b_msg
__device__ int    g_deg[N_NODES];
__device__ int    g_rank[N_EDGES];          // edge rank within its dst bucket
__device__ int    g_off[N_NODES + 1];
__device__ int    g_blksum[64];
__device__ int    g_csr_src[N_EDGES];
__device__ float4 g_csr_ea [N_EDGES];

// ---------------- CSR build ---------------------------------------------------
__global__ void count_deg_kernel(const int* __restrict__ ei) {
    int e = blockIdx.x * blockDim.x + threadIdx.x;
    if (e < N_EDGES) {
        int dst = ei[N_EDGES + e];
        g_rank[e] = atomicAdd(&g_deg[dst], 1);   // rank doubles as fill position
    }
}

__global__ __launch_bounds__(1024)
void scan_local_kernel() {
    __shared__ int warp_sums[32];
    int tid  = threadIdx.x;
    int lane = tid & 31;
    int wid  = tid >> 5;
    int v = blockIdx.x * 1024 + tid;
    int d = (v < N_NODES) ? g_deg[v] : 0;
    int x = d;
    #pragma unroll
    for (int o = 1; o < 32; o <<= 1) {
        int y = __shfl_up_sync(0xFFFFFFFFu, x, o);
        if (lane >= o) x += y;
    }
    if (lane == 31) warp_sums[wid] = x;
    __syncthreads();
    if (wid == 0) {
        int w = warp_sums[lane];
        #pragma unroll
        for (int o = 1; o < 32; o <<= 1) {
            int y = __shfl_up_sync(0xFFFFFFFFu, w, o);
            if (lane >= o) w += y;
        }
        warp_sums[lane] = w;
    }
    __syncthreads();
    int prefix = (wid > 0) ? warp_sums[wid - 1] : 0;
    if (v < N_NODES) g_off[v] = prefix + x - d;
    if (tid == 1023) g_blksum[blockIdx.x] = prefix + x;
}

// per-block: add prefix of earlier block sums (<=49 values, trivial serial sum)
__global__ __launch_bounds__(1024)
void scan_add_kernel() {
    __shared__ int base_s;
    int bid = blockIdx.x;
    if (threadIdx.x == 0) {
        int acc = 0;
        for (int i = 0; i < bid; ++i) acc += g_blksum[i];
        base_s = acc;
    }
    __syncthreads();
    int v = bid * 1024 + threadIdx.x;
    if (v < N_NODES) g_off[v] += base_s;
    if (v == 0) g_off[N_NODES] = N_EDGES;
}

__global__ void fill_csr_kernel(const int* __restrict__ ei,
                                const float* __restrict__ ea) {
    int e = blockIdx.x * blockDim.x + threadIdx.x;
    if (e >= N_EDGES) return;
    int src = ei[e];
    int dst = ei[N_EDGES + e];
    int pos = g_off[dst] + g_rank[e];      // atomic-free
    g_csr_src[pos] = src;
    g_csr_ea[pos]  = *(const float4*)(ea + (size_t)e * 4);
}

// ---------------- TF32 helpers (input projection only) -----------------------
__device__ __forceinline__ unsigned f2tf32(float x) {
    unsigned r;
    asm("cvt.rna.tf32.f32 %0, %1;" : "=r"(r) : "f"(x));
    return r;
}

#define MMA_TF32(c, a, b)                                                       \
    asm volatile(                                                               \
        "mma.sync.aligned.m16n8k8.row.col.f32.tf32.tf32.f32 "                   \
        "{%0,%1,%2,%3}, {%4,%5,%6,%7}, {%8,%9}, {%0,%1,%2,%3};\n"               \
        : "+f"((c)[0]), "+f"((c)[1]), "+f"((c)[2]), "+f"((c)[3])                \
        : "r"((a)[0]), "r"((a)[1]), "r"((a)[2]), "r"((a)[3]),                   \
          "r"((b)[0]), "r"((b)[1]))

#define MMA_F16(c, a, b)                                                        \
    asm volatile(                                                               \
        "mma.sync.aligned.m16n8k16.row.col.f32.f16.f16.f32 "                    \
        "{%0,%1,%2,%3}, {%4,%5,%6,%7}, {%8,%9}, {%0,%1,%2,%3};\n"               \
        : "+f"((c)[0]), "+f"((c)[1]), "+f"((c)[2]), "+f"((c)[3])                \
        : "r"((a)[0]), "r"((a)[1]), "r"((a)[2]), "r"((a)[3]),                   \
          "r"((b)[0]), "r"((b)[1]))

// ---------------- input projection GEMM (K=256, TF32, proven) ----------------
#define GBM 128
#define GBK 32

__global__ __launch_bounds__(256, 2)
void gemm_in_kernel(const float* __restrict__ A, const float* __restrict__ B0,
                    const float* __restrict__ bias0, float* __restrict__ C0,
                    int M, int K) {
    __shared__ unsigned As[8 * 4 * 32 * 4];
    __shared__ unsigned Bs[16 * 4 * 32 * 2];

    int tid  = threadIdx.x;
    int lane = tid & 31;
    int warp = tid >> 5;
    int warpM = warp >> 1;
    int warpN = warp & 1;
    int rowBase = blockIdx.x * GBM;

    float c[2][8][4] = {};

    int a_row = tid >> 1;
    int a_col = (tid & 1) * 16;
    bool arow_ok = (rowBase + a_row) < M;
    const float* Arow = A + (size_t)(rowBase + a_row) * K;
    int b_k = tid >> 3;
    int b_n = (tid & 7) * 16;

    float4 pa[4];
    #pragma unroll
    for (int j = 0; j < 4; ++j)
        pa[j] = arow_ok ? *(const float4*)(Arow + a_col + j * 4)
                        : make_float4(0.f, 0.f, 0.f, 0.f);

    const int a_m16   = a_row >> 4;
    const int a_jbit  = (a_row >> 3) & 1;
    const int a_lnrow = (a_row & 7) << 2;

    for (int k0 = 0; k0 < K; k0 += GBK) {
        #pragma unroll
        for (int j = 0; j < 4; ++j) {
            float v[4] = {pa[j].x, pa[j].y, pa[j].z, pa[j].w};
            #pragma unroll
            for (int t = 0; t < 4; ++t) {
                int k  = a_col + j * 4 + t;
                int kg = k >> 3;
                int ln = a_lnrow | (k & 3);
                int jj = a_jbit | (((k >> 2) & 1) << 1);
                As[(((a_m16 << 2) | kg) << 7) | (ln << 2) | jj] = f2tf32(v[t]);
            }
        }
        #pragma unroll
        for (int j = 0; j < 4; ++j) {
            float4 v = *(const float4*)(B0 + (size_t)(k0 + b_k) * 128 + b_n + j * 4);
            float vv[4] = {v.x, v.y, v.z, v.w};
            #pragma unroll
            for (int t = 0; t < 4; ++t) {
                int n  = b_n + j * 4 + t;
                int n8 = n >> 3;
                int kg = b_k >> 3;
                int ln = ((n & 7) << 2) | (b_k & 3);
                int jj = (b_k >> 2) & 1;
                Bs[(((n8 << 2) | kg) << 6) | (ln << 1) | jj] = f2tf32(vv[t]);
            }
        }
        __syncthreads();

        if (k0 + GBK < K) {
            #pragma unroll
            for (int j = 0; j < 4; ++j)
                pa[j] = arow_ok ? *(const float4*)(Arow + k0 + GBK + a_col + j * 4)
                                : make_float4(0.f, 0.f, 0.f, 0.f);
        }

        #pragma unroll
        for (int kg = 0; kg < 4; ++kg) {
            unsigned a[2][4], b[8][2];
            #pragma unroll
            for (int m = 0; m < 2; ++m) {
                int m16 = warpM * 2 + m;
                uint4 av = *(const uint4*)&As[(((m16 << 2) | kg) << 7) | (lane << 2)];
                a[m][0] = av.x; a[m][1] = av.y; a[m][2] = av.z; a[m][3] = av.w;
            }
            #pragma unroll
            for (int n = 0; n < 8; ++n) {
                int n8 = warpN * 8 + n;
                uint2 bv = *(const uint2*)&Bs[(((n8 << 2) | kg) << 6) | (lane << 1)];
                b[n][0] = bv.x; b[n][1] = bv.y;
            }
            #pragma unroll
            for (int m = 0; m < 2; ++m)
                #pragma unroll
                for (int n = 0; n < 8; ++n)
                    MMA_TF32(c[m][n], a[m], b[n]);
        }
        __syncthreads();
    }

    #pragma unroll
    for (int m = 0; m < 2; ++m) {
        int r0 = rowBase + warpM * 32 + m * 16 + (lane >> 2);
        #pragma unroll
        for (int n = 0; n < 8; ++n) {
            int col = warpN * 64 + n * 8 + (lane & 3) * 2;
            float bb0 = bias0[col];
            float bb1 = bias0[col + 1];
            if (r0 < M)
                *(float2*)(C0 + (size_t)r0 * 128 + col) =
                    make_float2(c[m][n][0] + bb0, c[m][n][1] + bb1);
            if (r0 + 8 < M)
                *(float2*)(C0 + (size_t)(r0 + 8) * 128 + col) =
                    make_float2(c[m][n][2] + bb0, c[m][n][3] + bb1);
        }
    }
}

// ---------------- fp16 fused layer GEMM: A staged once, P1(half) + P2 --------
// K = 128, m16n8k16. As frags 32KB + Bs frags 32KB = 64KB dynamic smem.
// MMA sweep per target runs with no intermediate syncs (full B staged).
#define LAYER_SMEM ((8 * 8 * 32 * 4 + 16 * 8 * 32 * 2) * 4)

__device__ __forceinline__ void storeAfragH(unsigned* As, int row, int k, unsigned v) {
    int kk = k & 15, kg = k >> 4;
    int lane = ((row & 7) << 2) | ((kk >> 1) & 3);
    int j = ((row >> 3) & 1) | (((kk >> 3) & 1) << 1);
    int m16 = row >> 4;
    As[(((((m16 << 3) | kg) << 5) | lane) << 2) | j] = v;
}

__global__ __launch_bounds__(256, 2)
void gemm_layer_f16_kernel(const float* __restrict__ A,
                           const float* __restrict__ B0, const float* __restrict__ B1,
                           const float* __restrict__ bias1,
                           __half* __restrict__ C0, float* __restrict__ C1, int M) {
    extern __shared__ unsigned sm[];
    unsigned* As = sm;           // [m16(8)][kg(8)][lane(32)][j(4)] half2
    unsigned* Bs = sm + 8192;    // [n8(16)][kg(8)][lane(32)][j(2)] half2

    int tid  = threadIdx.x;
    int lane = tid & 31;
    int warp = tid >> 5;
    int warpM = warp >> 1;
    int warpN = warp & 1;
    int rowBase = blockIdx.x * 128;

    // ---- stage A (128x128 fp32 -> fp16 frags), once ----
    {
        int row = tid >> 1;
        int cb  = (tid & 1) * 64;
        bool ok = (rowBase + row) < M;
        const float* Arow = A + (size_t)(rowBase + row) * 128;
        #pragma unroll
        for (int q = 0; q < 16; ++q) {
            int k = cb + q * 4;
            float4 v = ok ? *(const float4*)(Arow + k)
                          : make_float4(0.f, 0.f, 0.f, 0.f);
            __half2 h0 = __floats2half2_rn(v.x, v.y);
            __half2 h1 = __floats2half2_rn(v.z, v.w);
            storeAfragH(As, row, k,     *(unsigned*)&h0);
            storeAfragH(As, row, k + 2, *(unsigned*)&h1);
        }
    }

    #pragma unroll
    for (int t = 0; t < 2; ++t) {
        const float* B = t ? B1 : B0;

        // ---- stage full B (128x128 fp32 -> fp16 frags) ----
        // thread handles 8 (kpair, nchunk) slots: 2 LDG.128 + 4 STS each
        __syncthreads();   // As ready (t=0) / previous MMA done reading Bs (t=1)
        #pragma unroll
        for (int i = 0; i < 8; ++i) {
            int idx = tid + i * 256;          // 0..2047
            int kp  = idx >> 5;               // 0..63 (k pair)
            int nc  = (idx & 31) * 4;         // n chunk base
            int k0  = kp * 2;
            float4 r0 = *(const float4*)(B + (size_t)k0 * 128 + nc);
            float4 r1 = *(const float4*)(B + (size_t)(k0 + 1) * 128 + nc);
            float lo[4] = {r0.x, r0.y, r0.z, r0.w};
            float hi[4] = {r1.x, r1.y, r1.z, r1.w};
            int kk = k0 & 15, kg = k0 >> 4;
            int jb = (kk >> 3) & 1;
            int lnk = (kk >> 1) & 3;
            #pragma unroll
            for (int u = 0; u < 4; ++u) {
                int n = nc + u;
                __half2 hv = __floats2half2_rn(lo[u], hi[u]);
                int ln = ((n & 7) << 2) | lnk;
                Bs[((((((n >> 3) << 3) | kg) << 5) | ln) << 1) | jb] = *(unsigned*)&hv;
            }
        }
        __syncthreads();

        // ---- MMA sweep: 8 kg x 16 mma, no syncs ----
        float c[2][8][4] = {};
        #pragma unroll
        for (int kg = 0; kg < 8; ++kg) {
            unsigned a[2][4], b[8][2];
            #pragma unroll
            for (int m = 0; m < 2; ++m) {
                int m16 = warpM * 2 + m;
                uint4 av = *(const uint4*)&As[((((m16 << 3) | kg) << 5) | lane) << 2];
                a[m][0] = av.x; a[m][1] = av.y; a[m][2] = av.z; a[m][3] = av.w;
            }
            #pragma unroll
            for (int n = 0; n < 8; ++n) {
                int n8 = warpN * 8 + n;
                uint2 bv = *(const uint2*)&Bs[((((n8 << 3) | kg) << 5) | lane) << 1];
                b[n][0] = bv.x; b[n][1] = bv.y;
            }
            #pragma unroll
            for (int m = 0; m < 2; ++m)
                #pragma unroll
                for (int n = 0; n < 8; ++n)
                    MMA_F16(c[m][n], a[m], b[n]);
        }

        // ---- epilogue ----
        #pragma unroll
        for (int m = 0; m < 2; ++m) {
            int r0 = rowBase + warpM * 32 + m * 16 + (lane >> 2);
            #pragma unroll
            for (int n = 0; n < 8; ++n) {
                int col = warpN * 64 + n * 8 + (lane & 3) * 2;
                if (t == 0) {   // P1 -> fp16, no bias
                    if (r0 < M)
                        *(__half2*)(C0 + (size_t)r0 * 128 + col) =
                            __floats2half2_rn(c[m][n][0], c[m][n][1]);
                    if (r0 + 8 < M)
                        *(__half2*)(C0 + (size_t)(r0 + 8) * 128 + col) =
                            __floats2half2_rn(c[m][n][2], c[m][n][3]);
                } else {        // P2 -> fp32 + bias
                    float bb0 = bias1[col];
                    float bb1 = bias1[col + 1];
                    if (r0 < M)
                        *(float2*)(C1 + (size_t)r0 * 128 + col) =
                            make_float2(c[m][n][0] + bb0, c[m][n][1] + bb1);
                    if (r0 + 8 < M)
                        *(float2*)(C1 + (size_t)(r0 + 8) * 128 + col) =
                            make_float2(c[m][n][2] + bb0, c[m][n][3] + bb1);
                }
            }
        }
    }
}

// ---------------- edge message + aggregation (warp per dst node) -------------
__device__ __forceinline__ float4 loadP1h(const __half* __restrict__ P1,
                                          int s, int c4) {
    uint2 raw = *(const uint2*)(P1 + (size_t)s * HID + c4);
    __half2 h0 = *reinterpret_cast<__half2*>(&raw.x);
    __half2 h1 = *reinterpret_cast<__half2*>(&raw.y);
    float2 f0 = __half22float2(h0);
    float2 f1 = __half22float2(h1);
    return make_float4(f0.x, f0.y, f1.x, f1.y);
}

__global__ __launch_bounds__(256)
void edge_msg_kernel(const __half* __restrict__ P1, const float* __restrict__ P2,
                     const float* __restrict__ W3 /* [4,128] */) {
    int warp = (blockIdx.x * blockDim.x + threadIdx.x) >> 5;
    int lane = threadIdx.x & 31;
    if (warp >= N_NODES) return;
    int v = warp;
    int c4 = lane * 4;

    float4 w0 = *(const float4*)(W3 + 0 * HID + c4);
    float4 w1 = *(const float4*)(W3 + 1 * HID + c4);
    float4 w2 = *(const float4*)(W3 + 2 * HID + c4);
    float4 w3 = *(const float4*)(W3 + 3 * HID + c4);
    float4 p2 = *(const float4*)(P2 + (size_t)v * HID + c4);

    float4 acc = make_float4(0.f, 0.f, 0.f, 0.f);
    int e0 = g_off[v];
    int e1 = g_off[v + 1];
    int e  = e0;

    #define EDGE_ONE(p1v, eav)                                                        \
        do {                                                                          \
            float mx = (p1v).x + p2.x + (eav).x * w0.x + (eav).y * w1.x +             \
                       (eav).z * w2.x + (eav).w * w3.x;                               \
            float my = (p1v).y + p2.y + (eav).x * w0.y + (eav).y * w1.y +             \
                       (eav).z * w2.y + (eav).w * w3.y;                               \
            float mz = (p1v).z + p2.z + (eav).x * w0.z + (eav).y * w1.z +             \
                       (eav).z * w2.z + (eav).w * w3.z;                               \
            float mw = (p1v).w + p2.w + (eav).x * w0.w + (eav).y * w1.w +             \
                       (eav).z * w2.w + (eav).w * w3.w;                               \
            acc.x += fmaxf(mx, 0.f); acc.y += fmaxf(my, 0.f);                         \
            acc.z += fmaxf(mz, 0.f); acc.w += fmaxf(mw, 0.f);                         \
        } while (0)

    for (; e + 3 < e1; e += 4) {
        int s0 = __ldg(&g_csr_src[e]);
        int s1 = __ldg(&g_csr_src[e + 1]);
        int s2 = __ldg(&g_csr_src[e + 2]);
        int s3 = __ldg(&g_csr_src[e + 3]);
        float4 q0 = loadP1h(P1, s0, c4);
        float4 q1 = loadP1h(P1, s1, c4);
        float4 q2 = loadP1h(P1, s2, c4);
        float4 q3 = loadP1h(P1, s3, c4);
        float4 a0 = g_csr_ea[e];
        float4 a1 = g_csr_ea[e + 1];
        float4 a2 = g_csr_ea[e + 2];
        float4 a3 = g_csr_ea[e + 3];
        EDGE_ONE(q0, a0);
        EDGE_ONE(q1, a1);
        EDGE_ONE(q2, a2);
        EDGE_ONE(q3, a3);
    }
    for (; e < e1; ++e) {
        int s = __ldg(&g_csr_src[e]);
        float4 q = loadP1h(P1, s, c4);
        float4 a = g_csr_ea[e];
        EDGE_ONE(q, a);
    }
    #undef EDGE_ONE

    float4 xv = *(float4*)(g_x + (size_t)v * HID + c4);
    xv.x += acc.x; xv.y += acc.y; xv.z += acc.z; xv.w += acc.w;
    *(float4*)(g_x + (size_t)v * HID + c4) = xv;
}

// ---------------- output projection (warp per node) --------------------------
__global__ __launch_bounds__(256)
void out_proj_kernel(const float* __restrict__ Wout, const float* __restrict__ bout,
                     float* __restrict__ out) {
    int warp = (blockIdx.x * blockDim.x + threadIdx.x) >> 5;
    int lane = threadIdx.x & 31;
    if (warp >= N_NODES) return;
    int v = warp;

    float s0 = 0.f, s1 = 0.f, s2 = 0.f;
    #pragma unroll
    for (int k = lane; k < HID; k += 32) {
        float xv = g_x[(size_t)v * HID + k];
        s0 += xv * Wout[k * 3 + 0];
        s1 += xv * Wout[k * 3 + 1];
        s2 += xv * Wout[k * 3 + 2];
    }
    #pragma unroll
    for (int o = 16; o > 0; o >>= 1) {
        s0 += __shfl_xor_sync(0xFFFFFFFFu, s0, o);
        s1 += __shfl_xor_sync(0xFFFFFFFFu, s1, o);
        s2 += __shfl_xor_sync(0xFFFFFFFFu, s2, o);
    }
    if (lane == 0) {
        out[v * 3 + 0] = s0 + bout[0];
        out[v * 3 + 1] = s1 + bout[1];
        out[v * 3 + 2] = s2 + bout[2];
    }
}

// ---------------- launch ------------------------------------------------------
extern "C" void kernel_launch(void* const* d_in, const int* in_sizes, int n_in,
                              void* d_out, int out_size) {
    const float* h     = (const float*)d_in[0];
    const int*   ei    = (const int*)  d_in[1];
    const float* ea    = (const float*)d_in[2];
    const float* W_in  = (const float*)d_in[3];
    const float* b_in  = (const float*)d_in[4];
    const float* W_msg = (const float*)d_in[5];
    const float* b_msg = (const float*)d_in[6];
    const float* W_out = (const float*)d_in[7];
    const float* b_out = (const float*)d_in[8];
    float* out = (float*)d_out;

    float  *px, *pP2;
    __half *pP1h;
    int    *pdeg;
    cudaGetSymbolAddress((void**)&px,   g_x);
    cudaGetSymbolAddress((void**)&pP1h, g_P1h);
    cudaGetSymbolAddress((void**)&pP2,  g_P2);
    cudaGetSymbolAddress((void**)&pdeg, g_deg);

    cudaFuncSetAttribute(gemm_layer_f16_kernel,
                         cudaFuncAttributeMaxDynamicSharedMemorySize, LAYER_SMEM);

    cudaMemsetAsync(pdeg, 0, N_NODES * sizeof(int), 0);

    const int EB = (N_EDGES + 255) / 256;
    const int SB = (N_NODES + 1023) / 1024;   // 49
    count_deg_kernel<<<EB, 256>>>(ei);
    scan_local_kernel<<<SB, 1024>>>();
    scan_add_kernel<<<SB, 1024>>>();
    fill_csr_kernel<<<EB, 256>>>(ei, ea);

    const int MT = (N_NODES + GBM - 1) / GBM;   // 391

    // input projection: x = h @ W_in + b_in
    gemm_in_kernel<<<MT, 256>>>(h, W_in, b_in, px, N_NODES, IN_DIM);

    const int NODE_WARP_BLOCKS = (N_NODES * 32 + 255) / 256;
    for (int l = 0; l < N_LAYERS; ++l) {
        const float* Wl = W_msg + (size_t)l * (2 * HID + EDGE_DIM) * HID;
        gemm_layer_f16_kernel<<<MT, 256, LAYER_SMEM>>>(px, Wl, Wl + HID * HID,
                                                       b_msg + l * HID,
                                                       pP1h, pP2, N_NODES);
        edge_msg_kernel<<<NODE_WARP_BLOCKS, 256>>>(pP1h, pP2, Wl + 2 * HID * HID);
    }

    out_proj_kernel<<<NODE_WARP_BLOCKS, 256>>>(W_out, b_out, out);
}

// round 7
// speedup vs baseline: 2.1028x; 1.3141x over previous
#include <cuda_runtime.h>
#include <cuda_bf16.h>
#include <cuda_fp16.h>

#define N_NODES 50000
#define N_EDGES 800000
#define IN_DIM  256
#define HID     128
#define OUT_DIM 3
#define EDGE_DIM 4
#define N_LAYERS 4

// ---------------- static device scratch (no allocations allowed) -------------
__device__ float  g_x  [N_NODES * HID];
__device__ __half g_P1h[N_NODES * HID];     // x @ W1 in fp16 (gathered by edges)
__device__ float  g_P2 [N_NODES * HID];     // x @ W2 + b_msg
__device__ int    g_deg[N_NODES];
__device__ int    g_rank[N_EDGES];          // edge rank within its dst bucket
__device__ int    g_off[N_NODES + 1];
__device__ int    g_blksum[64];
__device__ int    g_csr_src[N_EDGES];
__device__ float4 g_csr_ea [N_EDGES];
// Precomputed fp16 B fragments in per-lane mma order:
//   layer weights: [layer(4)][target(2)][n8(16)][kg(8)][lane(32)] uint2
//   input weights: [n8(16)][kg(16)][lane(32)] uint2
__device__ uint2  g_Bfrag  [N_LAYERS * 2 * 16 * 8 * 32];
__device__ uint2  g_BfragIn[16 * 16 * 32];

// ---------------- CSR build ---------------------------------------------------
__global__ void count_deg_kernel(const int* __restrict__ ei) {
    int e = blockIdx.x * blockDim.x + threadIdx.x;
    if (e < N_EDGES) {
        int dst = ei[N_EDGES + e];
        g_rank[e] = atomicAdd(&g_deg[dst], 1);   // rank doubles as fill position
    }
}

__global__ __launch_bounds__(1024)
void scan_local_kernel() {
    __shared__ int warp_sums[32];
    int tid  = threadIdx.x;
    int lane = tid & 31;
    int wid  = tid >> 5;
    int v = blockIdx.x * 1024 + tid;
    int d = (v < N_NODES) ? g_deg[v] : 0;
    int x = d;
    #pragma unroll
    for (int o = 1; o < 32; o <<= 1) {
        int y = __shfl_up_sync(0xFFFFFFFFu, x, o);
        if (lane >= o) x += y;
    }
    if (lane == 31) warp_sums[wid] = x;
    __syncthreads();
    if (wid == 0) {
        int w = warp_sums[lane];
        #pragma unroll
        for (int o = 1; o < 32; o <<= 1) {
            int y = __shfl_up_sync(0xFFFFFFFFu, w, o);
            if (lane >= o) w += y;
        }
        warp_sums[lane] = w;
    }
    __syncthreads();
    int prefix = (wid > 0) ? warp_sums[wid - 1] : 0;
    if (v < N_NODES) g_off[v] = prefix + x - d;
    if (tid == 1023) g_blksum[blockIdx.x] = prefix + x;
}

__global__ __launch_bounds__(1024)
void scan_add_kernel() {
    __shared__ int base_s;
    int bid = blockIdx.x;
    if (threadIdx.x == 0) {
        int acc = 0;
        for (int i = 0; i < bid; ++i) acc += g_blksum[i];
        base_s = acc;
    }
    __syncthreads();
    int v = bid * 1024 + threadIdx.x;
    if (v < N_NODES) g_off[v] += base_s;
    if (v == 0) g_off[N_NODES] = N_EDGES;
}

__global__ void fill_csr_kernel(const int* __restrict__ ei,
                                const float* __restrict__ ea) {
    int e = blockIdx.x * blockDim.x + threadIdx.x;
    if (e >= N_EDGES) return;
    int src = ei[e];
    int dst = ei[N_EDGES + e];
    int pos = g_off[dst] + g_rank[e];      // atomic-free
    g_csr_src[pos] = src;
    g_csr_ea[pos]  = *(const float4*)(ea + (size_t)e * 4);
}

// ---------------- B-fragment precompute (runs once per launch) ---------------
__global__ void prep_bfrag_kernel(const float* __restrict__ W_in,
                                  const float* __restrict__ W_msg) {
    int idx  = blockIdx.x * blockDim.x + threadIdx.x;
    int lane = idx & 31;
    int rest = idx >> 5;
    const int NLAYER_ELEMS = N_LAYERS * 2 * 16 * 8;   // 1024 warp-slots
    if (rest < NLAYER_ELEMS) {
        int kg  = rest & 7;
        int n8  = (rest >> 3) & 15;
        int tgt = (rest >> 7) & 1;
        int l   = rest >> 8;
        const float* W = W_msg + (size_t)l * (2 * HID + EDGE_DIM) * HID
                               + (size_t)tgt * HID * HID;
        int n  = n8 * 8 + (lane >> 2);
        int k0 = kg * 16 + (lane & 3) * 2;
        __half2 b0 = __floats2half2_rn(W[(size_t)k0 * HID + n],
                                       W[(size_t)(k0 + 1) * HID + n]);
        __half2 b1 = __floats2half2_rn(W[(size_t)(k0 + 8) * HID + n],
                                       W[(size_t)(k0 + 9) * HID + n]);
        uint2 v;
        v.x = *(unsigned*)&b0;
        v.y = *(unsigned*)&b1;
        g_Bfrag[(size_t)rest * 32 + lane] = v;
    } else if (rest < NLAYER_ELEMS + 16 * 16) {
        int r2 = rest - NLAYER_ELEMS;
        int kg = r2 & 15;
        int n8 = r2 >> 4;
        int n  = n8 * 8 + (lane >> 2);
        int k0 = kg * 16 + (lane & 3) * 2;
        __half2 b0 = __floats2half2_rn(W_in[(size_t)k0 * HID + n],
                                       W_in[(size_t)(k0 + 1) * HID + n]);
        __half2 b1 = __floats2half2_rn(W_in[(size_t)(k0 + 8) * HID + n],
                                       W_in[(size_t)(k0 + 9) * HID + n]);
        uint2 v;
        v.x = *(unsigned*)&b0;
        v.y = *(unsigned*)&b1;
        g_BfragIn[(size_t)r2 * 32 + lane] = v;
    }
}

// ---------------- MMA helpers -------------------------------------------------
#define MMA_F16(c, a, b)                                                        \
    asm volatile(                                                               \
        "mma.sync.aligned.m16n8k16.row.col.f32.f16.f16.f32 "                    \
        "{%0,%1,%2,%3}, {%4,%5,%6,%7}, {%8,%9}, {%0,%1,%2,%3};\n"               \
        : "+f"((c)[0]), "+f"((c)[1]), "+f"((c)[2]), "+f"((c)[3])                \
        : "r"((a)[0]), "r"((a)[1]), "r"((a)[2]), "r"((a)[3]),                   \
          "r"((b)[0]), "r"((b)[1]))

__device__ __forceinline__ unsigned f2h2(float a, float b) {
    __half2 h = __floats2half2_rn(a, b);
    return *(unsigned*)&h;
}

// load one A fragment (4 regs) for mma.m16n8k16 directly from fp32 global
__device__ __forceinline__ void loadAfrag(unsigned a[4], const float* __restrict__ A,
                                          int r, int kc, int K, int M) {
    const float* Ar = A + (size_t)r * K + kc;
    bool ok0 = r < M, ok1 = (r + 8) < M;
    float2 v0 = ok0 ? *(const float2*)(Ar)             : make_float2(0.f, 0.f);
    float2 v1 = ok1 ? *(const float2*)(Ar + 8 * K)     : make_float2(0.f, 0.f);
    float2 v2 = ok0 ? *(const float2*)(Ar + 8)         : make_float2(0.f, 0.f);
    float2 v3 = ok1 ? *(const float2*)(Ar + 8 * K + 8) : make_float2(0.f, 0.f);
    a[0] = f2h2(v0.x, v0.y);
    a[1] = f2h2(v1.x, v1.y);
    a[2] = f2h2(v2.x, v2.y);
    a[3] = f2h2(v3.x, v3.y);
}

// ---------------- input projection GEMM (K=256), register-direct -------------
#define GBM 128

__global__ __launch_bounds__(256, 2)
void gemm_in_reg_kernel(const float* __restrict__ A,
                        const float* __restrict__ bias0,
                        float* __restrict__ C0, int M) {
    int tid  = threadIdx.x;
    int lane = tid & 31;
    int warp = tid >> 5;
    int warpM = warp >> 1;
    int warpN = warp & 1;
    int rowBase = blockIdx.x * GBM;

    float c[2][8][4] = {};

    #pragma unroll
    for (int kg = 0; kg < 16; ++kg) {
        int kc = kg * 16 + (lane & 3) * 2;
        unsigned a[2][4];
        #pragma unroll
        for (int m = 0; m < 2; ++m) {
            int r = rowBase + warpM * 32 + m * 16 + (lane >> 2);
            loadAfrag(a[m], A, r, kc, IN_DIM, M);
        }
        uint2 b[8];
        #pragma unroll
        for (int n = 0; n < 8; ++n) {
            int n8 = warpN * 8 + n;
            b[n] = g_BfragIn[(size_t)((n8 * 16 + kg) * 32 + lane)];
        }
        #pragma unroll
        for (int m = 0; m < 2; ++m)
            #pragma unroll
            for (int n = 0; n < 8; ++n)
                MMA_F16(c[m][n], a[m], (unsigned*)&b[n]);
    }

    #pragma unroll
    for (int m = 0; m < 2; ++m) {
        int r0 = rowBase + warpM * 32 + m * 16 + (lane >> 2);
        #pragma unroll
        for (int n = 0; n < 8; ++n) {
            int col = warpN * 64 + n * 8 + (lane & 3) * 2;
            float bb0 = bias0[col];
            float bb1 = bias0[col + 1];
            if (r0 < M)
                *(float2*)(C0 + (size_t)r0 * 128 + col) =
                    make_float2(c[m][n][0] + bb0, c[m][n][1] + bb1);
            if (r0 + 8 < M)
                *(float2*)(C0 + (size_t)(r0 + 8) * 128 + col) =
                    make_float2(c[m][n][2] + bb0, c[m][n][3] + bb1);
        }
    }
}

// ---------------- fused layer GEMM (K=128), register-direct ------------------
// Computes P1 = A@W1 (fp16 out) and P2 = A@W2 + bias (fp32 out) per block row.
__global__ __launch_bounds__(256, 2)
void gemm_layer_reg_kernel(const float* __restrict__ A,
                           const uint2* __restrict__ BfragL,  // [2][16][8][32]
                           const float* __restrict__ bias1,
                           __half* __restrict__ C0, float* __restrict__ C1,
                           int M) {
    int tid  = threadIdx.x;
    int lane = tid & 31;
    int warp = tid >> 5;
    int warpM = warp >> 1;
    int warpN = warp & 1;
    int rowBase = blockIdx.x * GBM;

    #pragma unroll
    for (int t = 0; t < 2; ++t) {
        const uint2* Bf = BfragL + (size_t)t * (16 * 8 * 32);
        float c[2][8][4] = {};

        #pragma unroll
        for (int kg = 0; kg < 8; ++kg) {
            int kc = kg * 16 + (lane & 3) * 2;
            unsigned a[2][4];
            #pragma unroll
            for (int m = 0; m < 2; ++m) {
                int r = rowBase + warpM * 32 + m * 16 + (lane >> 2);
                loadAfrag(a[m], A, r, kc, HID, M);
            }
            uint2 b[8];
            #pragma unroll
            for (int n = 0; n < 8; ++n) {
                int n8 = warpN * 8 + n;
                b[n] = Bf[(size_t)((n8 * 8 + kg) * 32 + lane)];
            }
            #pragma unroll
            for (int m = 0; m < 2; ++m)
                #pragma unroll
                for (int n = 0; n < 8; ++n)
                    MMA_F16(c[m][n], a[m], (unsigned*)&b[n]);
        }

        #pragma unroll
        for (int m = 0; m < 2; ++m) {
            int r0 = rowBase + warpM * 32 + m * 16 + (lane >> 2);
            #pragma unroll
            for (int n = 0; n < 8; ++n) {
                int col = warpN * 64 + n * 8 + (lane & 3) * 2;
                if (t == 0) {   // P1 -> fp16, no bias
                    if (r0 < M)
                        *(__half2*)(C0 + (size_t)r0 * 128 + col) =
                            __floats2half2_rn(c[m][n][0], c[m][n][1]);
                    if (r0 + 8 < M)
                        *(__half2*)(C0 + (size_t)(r0 + 8) * 128 + col) =
                            __floats2half2_rn(c[m][n][2], c[m][n][3]);
                } else {        // P2 -> fp32 + bias
                    float bb0 = bias1[col];
                    float bb1 = bias1[col + 1];
                    if (r0 < M)
                        *(float2*)(C1 + (size_t)r0 * 128 + col) =
                            make_float2(c[m][n][0] + bb0, c[m][n][1] + bb1);
                    if (r0 + 8 < M)
                        *(float2*)(C1 + (size_t)(r0 + 8) * 128 + col) =
                            make_float2(c[m][n][2] + bb0, c[m][n][3] + bb1);
                }
            }
        }
    }
}

// ---------------- edge message + aggregation (warp per dst node) -------------
__device__ __forceinline__ float4 loadP1h(const __half* __restrict__ P1,
                                          int s, int c4) {
    uint2 raw = *(const uint2*)(P1 + (size_t)s * HID + c4);
    __half2 h0 = *reinterpret_cast<__half2*>(&raw.x);
    __half2 h1 = *reinterpret_cast<__half2*>(&raw.y);
    float2 f0 = __half22float2(h0);
    float2 f1 = __half22float2(h1);
    return make_float4(f0.x, f0.y, f1.x, f1.y);
}

__global__ __launch_bounds__(256)
void edge_msg_kernel(const __half* __restrict__ P1, const float* __restrict__ P2,
                     const float* __restrict__ W3 /* [4,128] */) {
    int warp = (blockIdx.x * blockDim.x + threadIdx.x) >> 5;
    int lane = threadIdx.x & 31;
    if (warp >= N_NODES) return;
    int v = warp;
    int c4 = lane * 4;

    float4 w0 = *(const float4*)(W3 + 0 * HID + c4);
    float4 w1 = *(const float4*)(W3 + 1 * HID + c4);
    float4 w2 = *(const float4*)(W3 + 2 * HID + c4);
    float4 w3 = *(const float4*)(W3 + 3 * HID + c4);
    float4 p2 = *(const float4*)(P2 + (size_t)v * HID + c4);

    float4 acc = make_float4(0.f, 0.f, 0.f, 0.f);
    int e0 = g_off[v];
    int e1 = g_off[v + 1];
    int e  = e0;

    #define EDGE_ONE(p1v, eav)                                                        \
        do {                                                                          \
            float mx = (p1v).x + p2.x + (eav).x * w0.x + (eav).y * w1.x +             \
                       (eav).z * w2.x + (eav).w * w3.x;                               \
            float my = (p1v).y + p2.y + (eav).x * w0.y + (eav).y * w1.y +             \
                       (eav).z * w2.y + (eav).w * w3.y;                               \
            float mz = (p1v).z + p2.z + (eav).x * w0.z + (eav).y * w1.z +             \
                       (eav).z * w2.z + (eav).w * w3.z;                               \
            float mw = (p1v).w + p2.w + (eav).x * w0.w + (eav).y * w1.w +             \
                       (eav).z * w2.w + (eav).w * w3.w;                               \
            acc.x += fmaxf(mx, 0.f); acc.y += fmaxf(my, 0.f);                         \
            acc.z += fmaxf(mz, 0.f); acc.w += fmaxf(mw, 0.f);                         \
        } while (0)

    for (; e + 3 < e1; e += 4) {
        int s0 = __ldg(&g_csr_src[e]);
        int s1 = __ldg(&g_csr_src[e + 1]);
        int s2 = __ldg(&g_csr_src[e + 2]);
        int s3 = __ldg(&g_csr_src[e + 3]);
        float4 q0 = loadP1h(P1, s0, c4);
        float4 q1 = loadP1h(P1, s1, c4);
        float4 q2 = loadP1h(P1, s2, c4);
        float4 q3 = loadP1h(P1, s3, c4);
        float4 a0 = g_csr_ea[e];
        float4 a1 = g_csr_ea[e + 1];
        float4 a2 = g_csr_ea[e + 2];
        float4 a3 = g_csr_ea[e + 3];
        EDGE_ONE(q0, a0);
        EDGE_ONE(q1, a1);
        EDGE_ONE(q2, a2);
        EDGE_ONE(q3, a3);
    }
    for (; e < e1; ++e) {
        int s = __ldg(&g_csr_src[e]);
        float4 q = loadP1h(P1, s, c4);
        float4 a = g_csr_ea[e];
        EDGE_ONE(q, a);
    }
    #undef EDGE_ONE

    float4 xv = *(float4*)(g_x + (size_t)v * HID + c4);
    xv.x += acc.x; xv.y += acc.y; xv.z += acc.z; xv.w += acc.w;
    *(float4*)(g_x + (size_t)v * HID + c4) = xv;
}

// ---------------- output projection (warp per node) --------------------------
__global__ __launch_bounds__(256)
void out_proj_kernel(const float* __restrict__ Wout, const float* __restrict__ bout,
                     float* __restrict__ out) {
    int warp = (blockIdx.x * blockDim.x + threadIdx.x) >> 5;
    int lane = threadIdx.x & 31;
    if (warp >= N_NODES) return;
    int v = warp;

    float s0 = 0.f, s1 = 0.f, s2 = 0.f;
    #pragma unroll
    for (int k = lane; k < HID; k += 32) {
        float xv = g_x[(size_t)v * HID + k];
        s0 += xv * Wout[k * 3 + 0];
        s1 += xv * Wout[k * 3 + 1];
        s2 += xv * Wout[k * 3 + 2];
    }
    #pragma unroll
    for (int o = 16; o > 0; o >>= 1) {
        s0 += __shfl_xor_sync(0xFFFFFFFFu, s0, o);
        s1 += __shfl_xor_sync(0xFFFFFFFFu, s1, o);
        s2 += __shfl_xor_sync(0xFFFFFFFFu, s2, o);
    }
    if (lane == 0) {
        out[v * 3 + 0] = s0 + bout[0];
        out[v * 3 + 1] = s1 + bout[1];
        out[v * 3 + 2] = s2 + bout[2];
    }
}

// ---------------- launch ------------------------------------------------------
extern "C" void kernel_launch(void* const* d_in, const int* in_sizes, int n_in,
                              void* d_out, int out_size) {
    const float* h     = (const float*)d_in[0];
    const int*   ei    = (const int*)  d_in[1];
    const float* ea    = (const float*)d_in[2];
    const float* W_in  = (const float*)d_in[3];
    const float* b_in  = (const float*)d_in[4];
    const float* W_msg = (const float*)d_in[5];
    const float* b_msg = (const float*)d_in[6];
    const float* W_out = (const float*)d_in[7];
    const float* b_out = (const float*)d_in[8];
    float* out = (float*)d_out;

    float  *px, *pP2;
    __half *pP1h;
    int    *pdeg;
    uint2  *pBfrag;
    cudaGetSymbolAddress((void**)&px,    g_x);
    cudaGetSymbolAddress((void**)&pP1h,  g_P1h);
    cudaGetSymbolAddress((void**)&pP2,   g_P2);
    cudaGetSymbolAddress((void**)&pdeg,  g_deg);
    cudaGetSymbolAddress((void**)&pBfrag, g_Bfrag);

    cudaMemsetAsync(pdeg, 0, N_NODES * sizeof(int), 0);

    // B fragments for all layers + input projection (one small kernel)
    prep_bfrag_kernel<<<160, 256>>>(W_in, W_msg);

    const int EB = (N_EDGES + 255) / 256;
    const int SB = (N_NODES + 1023) / 1024;   // 49
    count_deg_kernel<<<EB, 256>>>(ei);
    scan_local_kernel<<<SB, 1024>>>();
    scan_add_kernel<<<SB, 1024>>>();
    fill_csr_kernel<<<EB, 256>>>(ei, ea);

    const int MT = (N_NODES + GBM - 1) / GBM;   // 391

    // input projection: x = h @ W_in + b_in
    gemm_in_reg_kernel<<<MT, 256>>>(h, b_in, px, N_NODES);

    const int NODE_WARP_BLOCKS = (N_NODES * 32 + 255) / 256;
    for (int l = 0; l < N_LAYERS; ++l) {
        const float* Wl = W_msg + (size_t)l * (2 * HID + EDGE_DIM) * HID;
        gemm_layer_reg_kernel<<<MT, 256>>>(px,
                                           pBfrag + (size_t)l * 2 * 16 * 8 * 32,
                                           b_msg + l * HID,
                                           pP1h, pP2, N_NODES);
        edge_msg_kernel<<<NODE_WARP_BLOCKS, 256>>>(pP1h, pP2, Wl + 2 * HID * HID);
    }

    out_proj_kernel<<<NODE_WARP_BLOCKS, 256>>>(W_out, b_out, out);
}

// round 8
// speedup vs baseline: 2.1156x; 1.0061x over previous
#include <cuda_runtime.h>
#include <cuda_bf16.h>
#include <cuda_fp16.h>

#define N_NODES 50000
#define N_EDGES 800000
#define IN_DIM  256
#define HID     128
#define OUT_DIM 3
#define EDGE_DIM 4
#define N_LAYERS 4

// ---------------- static device scratch (no allocations allowed) -------------
__device__ float  g_x  [N_NODES * HID];
__device__ __half g_P1h[N_NODES * HID];     // x @ W1 in fp16 (gathered by edges)
__device__ float  g_P2 [N_NODES * HID];     // x @ W2 + b_msg
__device__ int    g_deg[N_NODES];
__device__ int    g_rank[N_EDGES];          // edge rank within its dst bucket
__device__ int    g_off[N_NODES + 1];
__device__ int    g_blksum[64];
__device__ int    g_csr_src[N_EDGES];
__device__ float4 g_csr_ea [N_EDGES];
// Precomputed fp16 B fragments in per-lane mma order:
//   layer weights: [layer(4)][target(2)][n8(16)][kg(8)][lane(32)] uint2
//   input weights: [n8(16)][kg(16)][lane(32)] uint2
__device__ uint2  g_Bfrag  [N_LAYERS * 2 * 16 * 8 * 32];
__device__ uint2  g_BfragIn[16 * 16 * 32];

// ---------------- CSR build ---------------------------------------------------
__global__ void count_deg_kernel(const int* __restrict__ ei) {
    int e = blockIdx.x * blockDim.x + threadIdx.x;
    if (e < N_EDGES) {
        int dst = ei[N_EDGES + e];
        g_rank[e] = atomicAdd(&g_deg[dst], 1);   // rank doubles as fill position
    }
}

__global__ __launch_bounds__(1024)
void scan_local_kernel() {
    __shared__ int warp_sums[32];
    int tid  = threadIdx.x;
    int lane = tid & 31;
    int wid  = tid >> 5;
    int v = blockIdx.x * 1024 + tid;
    int d = (v < N_NODES) ? g_deg[v] : 0;
    int x = d;
    #pragma unroll
    for (int o = 1; o < 32; o <<= 1) {
        int y = __shfl_up_sync(0xFFFFFFFFu, x, o);
        if (lane >= o) x += y;
    }
    if (lane == 31) warp_sums[wid] = x;
    __syncthreads();
    if (wid == 0) {
        int w = warp_sums[lane];
        #pragma unroll
        for (int o = 1; o < 32; o <<= 1) {
            int y = __shfl_up_sync(0xFFFFFFFFu, w, o);
            if (lane >= o) w += y;
        }
        warp_sums[lane] = w;
    }
    __syncthreads();
    int prefix = (wid > 0) ? warp_sums[wid - 1] : 0;
    if (v < N_NODES) g_off[v] = prefix + x - d;
    if (tid == 1023) g_blksum[blockIdx.x] = prefix + x;
}

__global__ __launch_bounds__(1024)
void scan_add_kernel() {
    __shared__ int base_s;
    int bid = blockIdx.x;
    if (threadIdx.x == 0) {
        int acc = 0;
        for (int i = 0; i < bid; ++i) acc += g_blksum[i];
        base_s = acc;
    }
    __syncthreads();
    int v = bid * 1024 + threadIdx.x;
    if (v < N_NODES) g_off[v] += base_s;
    if (v == 0) g_off[N_NODES] = N_EDGES;
}

__global__ void fill_csr_kernel(const int* __restrict__ ei,
                                const float* __restrict__ ea) {
    int e = blockIdx.x * blockDim.x + threadIdx.x;
    if (e >= N_EDGES) return;
    int src = ei[e];
    int dst = ei[N_EDGES + e];
    int pos = g_off[dst] + g_rank[e];      // atomic-free
    g_csr_src[pos] = src;
    g_csr_ea[pos]  = *(const float4*)(ea + (size_t)e * 4);
}

// ---------------- B-fragment precompute (runs once per launch) ---------------
__global__ void prep_bfrag_kernel(const float* __restrict__ W_in,
                                  const float* __restrict__ W_msg) {
    int idx  = blockIdx.x * blockDim.x + threadIdx.x;
    int lane = idx & 31;
    int rest = idx >> 5;
    const int NLAYER_ELEMS = N_LAYERS * 2 * 16 * 8;   // 1024 warp-slots
    if (rest < NLAYER_ELEMS) {
        int kg  = rest & 7;
        int n8  = (rest >> 3) & 15;
        int tgt = (rest >> 7) & 1;
        int l   = rest >> 8;
        const float* W = W_msg + (size_t)l * (2 * HID + EDGE_DIM) * HID
                               + (size_t)tgt * HID * HID;
        int n  = n8 * 8 + (lane >> 2);
        int k0 = kg * 16 + (lane & 3) * 2;
        __half2 b0 = __floats2half2_rn(W[(size_t)k0 * HID + n],
                                       W[(size_t)(k0 + 1) * HID + n]);
        __half2 b1 = __floats2half2_rn(W[(size_t)(k0 + 8) * HID + n],
                                       W[(size_t)(k0 + 9) * HID + n]);
        uint2 v;
        v.x = *(unsigned*)&b0;
        v.y = *(unsigned*)&b1;
        g_Bfrag[(size_t)rest * 32 + lane] = v;
    } else if (rest < NLAYER_ELEMS + 16 * 16) {
        int r2 = rest - NLAYER_ELEMS;
        int kg = r2 & 15;
        int n8 = r2 >> 4;
        int n  = n8 * 8 + (lane >> 2);
        int k0 = kg * 16 + (lane & 3) * 2;
        __half2 b0 = __floats2half2_rn(W_in[(size_t)k0 * HID + n],
                                       W_in[(size_t)(k0 + 1) * HID + n]);
        __half2 b1 = __floats2half2_rn(W_in[(size_t)(k0 + 8) * HID + n],
                                       W_in[(size_t)(k0 + 9) * HID + n]);
        uint2 v;
        v.x = *(unsigned*)&b0;
        v.y = *(unsigned*)&b1;
        g_BfragIn[(size_t)r2 * 32 + lane] = v;
    }
}

// ---------------- MMA helpers -------------------------------------------------
#define MMA_F16(c, a, b)                                                        \
    asm volatile(                                                               \
        "mma.sync.aligned.m16n8k16.row.col.f32.f16.f16.f32 "                    \
        "{%0,%1,%2,%3}, {%4,%5,%6,%7}, {%8,%9}, {%0,%1,%2,%3};\n"               \
        : "+f"((c)[0]), "+f"((c)[1]), "+f"((c)[2]), "+f"((c)[3])                \
        : "r"((a)[0]), "r"((a)[1]), "r"((a)[2]), "r"((a)[3]),                   \
          "r"((b)[0]), "r"((b)[1]))

__device__ __forceinline__ unsigned f2h2(float a, float b) {
    __half2 h = __floats2half2_rn(a, b);
    return *(unsigned*)&h;
}

// load one A fragment (4 regs) for mma.m16n8k16 directly from fp32 global
__device__ __forceinline__ void loadAfrag(unsigned a[4], const float* __restrict__ A,
                                          int r, int kc, int K, int M) {
    const float* Ar = A + (size_t)r * K + kc;
    bool ok0 = r < M, ok1 = (r + 8) < M;
    float2 v0 = ok0 ? *(const float2*)(Ar)             : make_float2(0.f, 0.f);
    float2 v1 = ok1 ? *(const float2*)(Ar + 8 * K)     : make_float2(0.f, 0.f);
    float2 v2 = ok0 ? *(const float2*)(Ar + 8)         : make_float2(0.f, 0.f);
    float2 v3 = ok1 ? *(const float2*)(Ar + 8 * K + 8) : make_float2(0.f, 0.f);
    a[0] = f2h2(v0.x, v0.y);
    a[1] = f2h2(v1.x, v1.y);
    a[2] = f2h2(v2.x, v2.y);
    a[3] = f2h2(v3.x, v3.y);
}

// ---------------- input projection GEMM (K=256), register-direct -------------
#define GBM 128

__global__ __launch_bounds__(256, 2)
void gemm_in_reg_kernel(const float* __restrict__ A,
                        const float* __restrict__ bias0,
                        float* __restrict__ C0, int M) {
    int tid  = threadIdx.x;
    int lane = tid & 31;
    int warp = tid >> 5;
    int warpM = warp >> 1;
    int warpN = warp & 1;
    int rowBase = blockIdx.x * GBM;

    float c[2][8][4] = {};

    #pragma unroll
    for (int kg = 0; kg < 16; ++kg) {
        int kc = kg * 16 + (lane & 3) * 2;
        unsigned a[2][4];
        #pragma unroll
        for (int m = 0; m < 2; ++m) {
            int r = rowBase + warpM * 32 + m * 16 + (lane >> 2);
            loadAfrag(a[m], A, r, kc, IN_DIM, M);
        }
        uint2 b[8];
        #pragma unroll
        for (int n = 0; n < 8; ++n) {
            int n8 = warpN * 8 + n;
            b[n] = g_BfragIn[(size_t)((n8 * 16 + kg) * 32 + lane)];
        }
        #pragma unroll
        for (int m = 0; m < 2; ++m)
            #pragma unroll
            for (int n = 0; n < 8; ++n)
                MMA_F16(c[m][n], a[m], (unsigned*)&b[n]);
    }

    #pragma unroll
    for (int m = 0; m < 2; ++m) {
        int r0 = rowBase + warpM * 32 + m * 16 + (lane >> 2);
        #pragma unroll
        for (int n = 0; n < 8; ++n) {
            int col = warpN * 64 + n * 8 + (lane & 3) * 2;
            float bb0 = bias0[col];
            float bb1 = bias0[col + 1];
            if (r0 < M)
                *(float2*)(C0 + (size_t)r0 * 128 + col) =
                    make_float2(c[m][n][0] + bb0, c[m][n][1] + bb1);
            if (r0 + 8 < M)
                *(float2*)(C0 + (size_t)(r0 + 8) * 128 + col) =
                    make_float2(c[m][n][2] + bb0, c[m][n][3] + bb1);
        }
    }
}

// ---------------- fused layer GEMM (K=128), register-direct ------------------
__global__ __launch_bounds__(256, 2)
void gemm_layer_reg_kernel(const float* __restrict__ A,
                           const uint2* __restrict__ BfragL,  // [2][16][8][32]
                           const float* __restrict__ bias1,
                           __half* __restrict__ C0, float* __restrict__ C1,
                           int M) {
    int tid  = threadIdx.x;
    int lane = tid & 31;
    int warp = tid >> 5;
    int warpM = warp >> 1;
    int warpN = warp & 1;
    int rowBase = blockIdx.x * GBM;

    #pragma unroll
    for (int t = 0; t < 2; ++t) {
        const uint2* Bf = BfragL + (size_t)t * (16 * 8 * 32);
        float c[2][8][4] = {};

        #pragma unroll
        for (int kg = 0; kg < 8; ++kg) {
            int kc = kg * 16 + (lane & 3) * 2;
            unsigned a[2][4];
            #pragma unroll
            for (int m = 0; m < 2; ++m) {
                int r = rowBase + warpM * 32 + m * 16 + (lane >> 2);
                loadAfrag(a[m], A, r, kc, HID, M);
            }
            uint2 b[8];
            #pragma unroll
            for (int n = 0; n < 8; ++n) {
                int n8 = warpN * 8 + n;
                b[n] = Bf[(size_t)((n8 * 8 + kg) * 32 + lane)];
            }
            #pragma unroll
            for (int m = 0; m < 2; ++m)
                #pragma unroll
                for (int n = 0; n < 8; ++n)
                    MMA_F16(c[m][n], a[m], (unsigned*)&b[n]);
        }

        #pragma unroll
        for (int m = 0; m < 2; ++m) {
            int r0 = rowBase + warpM * 32 + m * 16 + (lane >> 2);
            #pragma unroll
            for (int n = 0; n < 8; ++n) {
                int col = warpN * 64 + n * 8 + (lane & 3) * 2;
                if (t == 0) {   // P1 -> fp16, no bias
                    if (r0 < M)
                        *(__half2*)(C0 + (size_t)r0 * 128 + col) =
                            __floats2half2_rn(c[m][n][0], c[m][n][1]);
                    if (r0 + 8 < M)
                        *(__half2*)(C0 + (size_t)(r0 + 8) * 128 + col) =
                            __floats2half2_rn(c[m][n][2], c[m][n][3]);
                } else {        // P2 -> fp32 + bias
                    float bb0 = bias1[col];
                    float bb1 = bias1[col + 1];
                    if (r0 < M)
                        *(float2*)(C1 + (size_t)r0 * 128 + col) =
                            make_float2(c[m][n][0] + bb0, c[m][n][1] + bb1);
                    if (r0 + 8 < M)
                        *(float2*)(C1 + (size_t)(r0 + 8) * 128 + col) =
                            make_float2(c[m][n][2] + bb0, c[m][n][3] + bb1);
                }
            }
        }
    }
}

// ---------------- edge message + aggregation (warp per dst node) -------------
__device__ __forceinline__ float4 loadP1h(const __half* __restrict__ P1,
                                          int s, int c4) {
    uint2 raw = *(const uint2*)(P1 + (size_t)s * HID + c4);
    __half2 h0 = *reinterpret_cast<__half2*>(&raw.x);
    __half2 h1 = *reinterpret_cast<__half2*>(&raw.y);
    float2 f0 = __half22float2(h0);
    float2 f1 = __half22float2(h1);
    return make_float4(f0.x, f0.y, f1.x, f1.y);
}

// core edge accumulation loop, unrolled by 8 for MLP
#define EDGE_ONE(p1v, eav)                                                        \
    do {                                                                          \
        float mx = (p1v).x + p2.x + (eav).x * w0.x + (eav).y * w1.x +             \
                   (eav).z * w2.x + (eav).w * w3.x;                               \
        float my = (p1v).y + p2.y + (eav).x * w0.y + (eav).y * w1.y +             \
                   (eav).z * w2.y + (eav).w * w3.y;                               \
        float mz = (p1v).z + p2.z + (eav).x * w0.z + (eav).y * w1.z +             \
                   (eav).z * w2.z + (eav).w * w3.z;                               \
        float mw = (p1v).w + p2.w + (eav).x * w0.w + (eav).y * w1.w +             \
                   (eav).z * w2.w + (eav).w * w3.w;                               \
        acc.x += fmaxf(mx, 0.f); acc.y += fmaxf(my, 0.f);                         \
        acc.z += fmaxf(mz, 0.f); acc.w += fmaxf(mw, 0.f);                         \
    } while (0)

#define EDGE_ACCUM_BODY                                                           \
    float4 acc = make_float4(0.f, 0.f, 0.f, 0.f);                                 \
    int e0 = g_off[v];                                                            \
    int e1 = g_off[v + 1];                                                        \
    int e  = e0;                                                                  \
    for (; e + 7 < e1; e += 8) {                                                  \
        int    s[8];                                                              \
        float4 q[8], aa[8];                                                       \
        _Pragma("unroll")                                                         \
        for (int i = 0; i < 8; ++i) s[i] = __ldg(&g_csr_src[e + i]);              \
        _Pragma("unroll")                                                         \
        for (int i = 0; i < 8; ++i) q[i] = loadP1h(P1, s[i], c4);                 \
        _Pragma("unroll")                                                         \
        for (int i = 0; i < 8; ++i) aa[i] = g_csr_ea[e + i];                      \
        _Pragma("unroll")                                                         \
        for (int i = 0; i < 8; ++i) EDGE_ONE(q[i], aa[i]);                        \
    }                                                                             \
    for (; e + 3 < e1; e += 4) {                                                  \
        int    s[4];                                                              \
        float4 q[4], aa[4];                                                       \
        _Pragma("unroll")                                                         \
        for (int i = 0; i < 4; ++i) s[i] = __ldg(&g_csr_src[e + i]);              \
        _Pragma("unroll")                                                         \
        for (int i = 0; i < 4; ++i) q[i] = loadP1h(P1, s[i], c4);                 \
        _Pragma("unroll")                                                         \
        for (int i = 0; i < 4; ++i) aa[i] = g_csr_ea[e + i];                      \
        _Pragma("unroll")                                                         \
        for (int i = 0; i < 4; ++i) EDGE_ONE(q[i], aa[i]);                        \
    }                                                                             \
    for (; e < e1; ++e) {                                                         \
        int    s  = __ldg(&g_csr_src[e]);                                         \
        float4 q  = loadP1h(P1, s, c4);                                           \
        float4 aa = g_csr_ea[e];                                                  \
        EDGE_ONE(q, aa);                                                          \
    }

__global__ __launch_bounds__(256)
void edge_msg_kernel(const __half* __restrict__ P1, const float* __restrict__ P2,
                     const float* __restrict__ W3 /* [4,128] */) {
    int warp = (blockIdx.x * blockDim.x + threadIdx.x) >> 5;
    int lane = threadIdx.x & 31;
    if (warp >= N_NODES) return;
    int v = warp;
    int c4 = lane * 4;

    float4 w0 = *(const float4*)(W3 + 0 * HID + c4);
    float4 w1 = *(const float4*)(W3 + 1 * HID + c4);
    float4 w2 = *(const float4*)(W3 + 2 * HID + c4);
    float4 w3 = *(const float4*)(W3 + 3 * HID + c4);
    float4 p2 = *(const float4*)(P2 + (size_t)v * HID + c4);

    EDGE_ACCUM_BODY

    float4 xv = *(float4*)(g_x + (size_t)v * HID + c4);
    xv.x += acc.x; xv.y += acc.y; xv.z += acc.z; xv.w += acc.w;
    *(float4*)(g_x + (size_t)v * HID + c4) = xv;
}

// last layer: fuse output projection; never writes g_x (saves full RW pass)
__global__ __launch_bounds__(256)
void edge_msg_out_kernel(const __half* __restrict__ P1, const float* __restrict__ P2,
                         const float* __restrict__ W3,
                         const float* __restrict__ Wout,
                         const float* __restrict__ bout,
                         float* __restrict__ out) {
    int warp = (blockIdx.x * blockDim.x + threadIdx.x) >> 5;
    int lane = threadIdx.x & 31;
    if (warp >= N_NODES) return;
    int v = warp;
    int c4 = lane * 4;

    float4 w0 = *(const float4*)(W3 + 0 * HID + c4);
    float4 w1 = *(const float4*)(W3 + 1 * HID + c4);
    float4 w2 = *(const float4*)(W3 + 2 * HID + c4);
    float4 w3 = *(const float4*)(W3 + 3 * HID + c4);
    float4 p2 = *(const float4*)(P2 + (size_t)v * HID + c4);

    EDGE_ACCUM_BODY

    float4 xv = *(float4*)(g_x + (size_t)v * HID + c4);
    xv.x += acc.x; xv.y += acc.y; xv.z += acc.z; xv.w += acc.w;

    // output projection from in-register xv: out[v] = xv . Wout[:,0..2] + bout
    // lane owns dims c4..c4+3; Wout is [128,3] row-major
    float s0 = xv.x * Wout[(c4 + 0) * 3 + 0] + xv.y * Wout[(c4 + 1) * 3 + 0]
             + xv.z * Wout[(c4 + 2) * 3 + 0] + xv.w * Wout[(c4 + 3) * 3 + 0];
    float s1 = xv.x * Wout[(c4 + 0) * 3 + 1] + xv.y * Wout[(c4 + 1) * 3 + 1]
             + xv.z * Wout[(c4 + 2) * 3 + 1] + xv.w * Wout[(c4 + 3) * 3 + 1];
    float s2 = xv.x * Wout[(c4 + 0) * 3 + 2] + xv.y * Wout[(c4 + 1) * 3 + 2]
             + xv.z * Wout[(c4 + 2) * 3 + 2] + xv.w * Wout[(c4 + 3) * 3 + 2];
    #pragma unroll
    for (int o = 16; o > 0; o >>= 1) {
        s0 += __shfl_xor_sync(0xFFFFFFFFu, s0, o);
        s1 += __shfl_xor_sync(0xFFFFFFFFu, s1, o);
        s2 += __shfl_xor_sync(0xFFFFFFFFu, s2, o);
    }
    if (lane == 0) {
        out[v * 3 + 0] = s0 + bout[0];
        out[v * 3 + 1] = s1 + bout[1];
        out[v * 3 + 2] = s2 + bout[2];
    }
}

// ---------------- launch ------------------------------------------------------
extern "C" void kernel_launch(void* const* d_in, const int* in_sizes, int n_in,
                              void* d_out, int out_size) {
    const float* h     = (const float*)d_in[0];
    const int*   ei    = (const int*)  d_in[1];
    const float* ea    = (const float*)d_in[2];
    const float* W_in  = (const float*)d_in[3];
    const float* b_in  = (const float*)d_in[4];
    const float* W_msg = (const float*)d_in[5];
    const float* b_msg = (const float*)d_in[6];
    const float* W_out = (const float*)d_in[7];
    const float* b_out = (const float*)d_in[8];
    float* out = (float*)d_out;

    float  *px, *pP2;
    __half *pP1h;
    int    *pdeg;
    uint2  *pBfrag;
    cudaGetSymbolAddress((void**)&px,    g_x);
    cudaGetSymbolAddress((void**)&pP1h,  g_P1h);
    cudaGetSymbolAddress((void**)&pP2,   g_P2);
    cudaGetSymbolAddress((void**)&pdeg,  g_deg);
    cudaGetSymbolAddress((void**)&pBfrag, g_Bfrag);

    cudaMemsetAsync(pdeg, 0, N_NODES * sizeof(int), 0);

    prep_bfrag_kernel<<<160, 256>>>(W_in, W_msg);

    const int EB = (N_EDGES + 255) / 256;
    const int SB = (N_NODES + 1023) / 1024;   // 49
    count_deg_kernel<<<EB, 256>>>(ei);
    scan_local_kernel<<<SB, 1024>>>();
    scan_add_kernel<<<SB, 1024>>>();
    fill_csr_kernel<<<EB, 256>>>(ei, ea);

    const int MT = (N_NODES + GBM - 1) / GBM;   // 391

    gemm_in_reg_kernel<<<MT, 256>>>(h, b_in, px, N_NODES);

    const int NODE_WARP_BLOCKS = (N_NODES * 32 + 255) / 256;
    for (int l = 0; l < N_LAYERS; ++l) {
        const float* Wl = W_msg + (size_t)l * (2 * HID + EDGE_DIM) * HID;
        gemm_layer_reg_kernel<<<MT, 256>>>(px,
                                           pBfrag + (size_t)l * 2 * 16 * 8 * 32,
                                           b_msg + l * HID,
                                           pP1h, pP2, N_NODES);
        if (l < N_LAYERS - 1) {
            edge_msg_kernel<<<NODE_WARP_BLOCKS, 256>>>(pP1h, pP2,
                                                       Wl + 2 * HID * HID);
        } else {
            edge_msg_out_kernel<<<NODE_WARP_BLOCKS, 256>>>(pP1h, pP2,
                                                           Wl + 2 * HID * HID,
                                                           W_out, b_out, out);
        }
    }
}